// round 6
// baseline (speedup 1.0000x reference)
#include <cuda_runtime.h>

#define B_     32
#define N_     577
#define L_     576
#define DIM_   512
#define HEADS_ 8
#define DH_    64
#define NDIM_  16
#define INNER_ 512
#define M_ROWS (B_ * N_)   // 18464
#define CH_    16          // EMA chunks
#define CL_    36          // EMA chunk length (16*36 = 576)

// -------- scratch (device globals) --------
__device__ float g_xm[(size_t)B_ * N_ * DIM_];
__device__ float g_qk[(size_t)B_ * N_ * 2 * INNER_];
__device__ float g_v [(size_t)B_ * N_ * INNER_];
__device__ float g_ao[(size_t)B_ * N_ * INNER_];
__device__ float g_cq[NDIM_][2 * DIM_];
__device__ float g_cc[NDIM_][2 * DIM_];
__device__ float g_sf[(size_t)B_ * CH_ * NDIM_ * DIM_];
__device__ float g_sb[(size_t)B_ * CH_ * NDIM_ * DIM_];
__device__ float g_wqk[512 * 1024];
__device__ float g_wv [512 * 512];
__device__ float g_wo [512 * 512];

// ---------------- helpers ----------------
__device__ __forceinline__ unsigned f2tf(float x) {
    unsigned u;
    asm("cvt.rna.tf32.f32 %0, %1;" : "=r"(u) : "f"(x));
    return u;
}
__device__ __forceinline__ float f2tff(float x) { return __uint_as_float(f2tf(x)); }

__device__ __forceinline__ void mma8(float* c, const unsigned* a, unsigned b0, unsigned b1) {
    asm volatile(
        "mma.sync.aligned.m16n8k8.row.col.f32.tf32.tf32.f32 "
        "{%0,%1,%2,%3},{%4,%5,%6,%7},{%8,%9},{%0,%1,%2,%3};"
        : "+f"(c[0]), "+f"(c[1]), "+f"(c[2]), "+f"(c[3])
        : "r"(a[0]), "r"(a[1]), "r"(a[2]), "r"(a[3]), "r"(b0), "r"(b1));
}

__device__ __forceinline__ unsigned s2u(const void* p) {
    return (unsigned)__cvta_generic_to_shared(p);
}
__device__ __forceinline__ void cp16(unsigned dst, const void* src, int srcsz) {
    asm volatile("cp.async.cg.shared.global [%0], [%1], 16, %2;"
                 :: "r"(dst), "l"(src), "r"(srcsz));
}
#define CP_COMMIT() asm volatile("cp.async.commit_group;")
#define CP_WAIT1()  asm volatile("cp.async.wait_group 1;")

__device__ __forceinline__ float pow36f(float q) {
    float q2 = q * q, q4 = q2 * q2, q8 = q4 * q4, q16 = q8 * q8, q32 = q16 * q16;
    return q32 * q4;
}

// ================= Stage 0: EMA coefficients + weight rounding =================
__global__ void coef_kernel(const float* __restrict__ delta, const float* __restrict__ alpha,
                            const float* __restrict__ beta,  const float* __restrict__ gamma) {
    int idx = blockIdx.x * blockDim.x + threadIdx.x;
    if (idx >= 2 * DIM_ * NDIM_) return;
    int d = idx / NDIM_;
    int n = idx % NDIM_;
    float p  = 1.f / (1.f + expf(-delta[idx]));
    float sa = 1.f / (1.f + expf(-alpha[idx]));
    g_cq[n][d] = 1.f - p * sa;
    g_cc[n][d] = p * beta[idx] * gamma[idx] * 0.25f;
}

__global__ void wcvt_kernel(const float* __restrict__ wqk, const float* __restrict__ wv,
                            const float* __restrict__ wo) {
    int i = blockIdx.x * 256 + threadIdx.x;
    if (i < 512 * 1024) g_wqk[i] = f2tff(wqk[i]);
    if (i < 512 * 512) {
        g_wv[i] = f2tff(wv[i]);
        g_wo[i] = f2tff(wo[i]);
    }
}

// ================= Stage 1a: chunk-local EMA scans (tree-sum) =================
__global__ void ema1_kernel(const float* __restrict__ x) {
    int d = blockIdx.x * 128 + threadIdx.x;
    int c = blockIdx.y, b = blockIdx.z;
    const float* xb = x    + (size_t)b * N_ * DIM_;
    float*       yb = g_xm + (size_t)b * N_ * DIM_;
    if (c == 0) yb[d] = f2tff(xb[d]);   // cls passthrough

    float q1[NDIM_], c1[NDIM_], q2[NDIM_], c2[NDIM_], s[NDIM_];
#pragma unroll
    for (int n = 0; n < NDIM_; n++) {
        q1[n] = g_cq[n][d];         c1[n] = g_cc[n][d];
        q2[n] = g_cq[n][d + DIM_];  c2[n] = g_cc[n][d + DIM_];
        s[n] = 0.f;
    }
    int t0 = c * CL_;
#pragma unroll 4
    for (int tl = 0; tl < CL_; tl++) {
        size_t idx = (size_t)(t0 + tl + 1) * DIM_ + d;
        float xv = xb[idx];
        float a[4] = {0.f, 0.f, 0.f, 0.f};
#pragma unroll
        for (int n = 0; n < NDIM_; n++) { s[n] = q1[n] * s[n] + xv; a[n >> 2] += c1[n] * s[n]; }
        yb[idx] = (a[0] + a[1]) + (a[2] + a[3]);
    }
#pragma unroll
    for (int n = 0; n < NDIM_; n++) {
        g_sf[(((size_t)b * CH_ + c) * NDIM_ + n) * DIM_ + d] = s[n];
        s[n] = 0.f;
    }
#pragma unroll 4
    for (int tl = CL_ - 1; tl >= 0; tl--) {
        size_t idx = (size_t)(t0 + tl + 1) * DIM_ + d;
        float xv = xb[idx];
        float a[4] = {0.f, 0.f, 0.f, 0.f};
#pragma unroll
        for (int n = 0; n < NDIM_; n++) { s[n] = q2[n] * s[n] + xv; a[n >> 2] += c2[n] * s[n]; }
        yb[idx] += (a[0] + a[1]) + (a[2] + a[3]);
    }
#pragma unroll
    for (int n = 0; n < NDIM_; n++)
        g_sb[(((size_t)b * CH_ + c) * NDIM_ + n) * DIM_ + d] = s[n];
}

// ================= Stage 1b: chunk-state prefix/suffix scan =================
// thread = (b, n, d). In-place: g_sf[c] <- incoming fwd state for chunk c,
// g_sb[c] <- incoming bwd state for chunk c.
__global__ void ema_scan_kernel() {
    int d = blockIdx.x * 128 + threadIdx.x;   // 0..511
    int n = blockIdx.y, b = blockIdx.z;
    float q1p = pow36f(g_cq[n][d]);
    float q2p = pow36f(g_cq[n][d + DIM_]);
    size_t base = ((size_t)b * CH_ * NDIM_ + n) * DIM_ + d;
    size_t step = (size_t)NDIM_ * DIM_;

    float Sin = 0.f;
    for (int c = 0; c < CH_; c++) {
        size_t idx = base + (size_t)c * step;
        float st = g_sf[idx];
        g_sf[idx] = Sin;
        Sin = q1p * Sin + st;
    }
    float Tin = 0.f;
    for (int c = CH_ - 1; c >= 0; c--) {
        size_t idx = base + (size_t)c * step;
        float st = g_sb[idx];
        g_sb[idx] = Tin;
        Tin = q2p * Tin + st;
    }
}

// ================= Stage 1c: cross-chunk corrections + silu (tree-sum) =================
__global__ void ema2_kernel(const float* __restrict__ x, const float* __restrict__ omega) {
    int d = blockIdx.x * 128 + threadIdx.x;
    int c = blockIdx.y, b = blockIdx.z;
    const float* xb = x    + (size_t)b * N_ * DIM_;
    float*       yb = g_xm + (size_t)b * N_ * DIM_;
    int t0 = c * CL_;

    // descending pass: backward correction  wv[tl] = c2 * q2^{CL-tl} * Sb_in
    if (c < CH_ - 1) {
        float q2[NDIM_], wv[NDIM_];
#pragma unroll
        for (int n = 0; n < NDIM_; n++) {
            q2[n] = g_cq[n][d + DIM_];
            float sb = g_sb[(((size_t)b * CH_ + c) * NDIM_ + n) * DIM_ + d];
            wv[n] = g_cc[n][d + DIM_] * sb * q2[n];
        }
#pragma unroll 4
        for (int tl = CL_ - 1; tl >= 0; tl--) {
            size_t idx = (size_t)(t0 + tl + 1) * DIM_ + d;
            float a[4] = {0.f, 0.f, 0.f, 0.f};
#pragma unroll
            for (int n = 0; n < NDIM_; n++) { a[n >> 2] += wv[n]; wv[n] *= q2[n]; }
            yb[idx] += (a[0] + a[1]) + (a[2] + a[3]);
        }
    }
    // ascending pass: forward correction + silu(y + x*omega), rounded for GEMM A
    {
        float q1[NDIM_], sv[NDIM_];
#pragma unroll
        for (int n = 0; n < NDIM_; n++) {
            q1[n] = g_cq[n][d];
            float sf = g_sf[(((size_t)b * CH_ + c) * NDIM_ + n) * DIM_ + d];
            sv[n] = g_cc[n][d] * sf;
        }
        float om = omega[d];
#pragma unroll 4
        for (int tl = 0; tl < CL_; tl++) {
            size_t idx = (size_t)(t0 + tl + 1) * DIM_ + d;
            float a[4] = {0.f, 0.f, 0.f, 0.f};
#pragma unroll
            for (int n = 0; n < NDIM_; n++) { sv[n] *= q1[n]; a[n >> 2] += sv[n]; }
            float u = yb[idx] + ((a[0] + a[1]) + (a[2] + a[3])) + xb[idx] * om;
            yb[idx] = f2tff(u / (1.f + __expf(-u)));
        }
    }
}

// ================= tf32 GEMM: 128x128 CTA, 4 warps 64x64, cp.async 3-stage =================
#define ASLAB (128 * 36)
#define BSLAB (32 * 136)
#define GSMEM_BYTES (3 * (ASLAB + BSLAB) * 4)

__device__ __forceinline__ void gemm_tc_body(const float* __restrict__ A, const float* __restrict__ Bm,
                                             float* __restrict__ C, int M, int Nn,
                                             const float* __restrict__ bias, int bnb, bool rnd) {
    extern __shared__ float gsm[];
    float* As = gsm;
    float* Bs = gsm + 3 * ASLAB;
    unsigned as_u = s2u(As), bs_u = s2u(Bs);

    int tid = threadIdx.x, lane = tid & 31, w = tid >> 5;
    int gr = lane >> 2, tg = lane & 3;
    int wm = w & 1, wn = w >> 1;
    int bm = blockIdx.y * 128, bn = bnb * 128;

#define GEMM_ISSUE(s)                                                                  \
    do {                                                                               \
        int _buf = (s) % 3, _k0 = (s) * 32;                                            \
        unsigned _ad = as_u + (unsigned)(_buf * ASLAB * 4);                            \
        unsigned _bd = bs_u + (unsigned)(_buf * BSLAB * 4);                            \
        _Pragma("unroll")                                                              \
        for (int it = 0; it < 8; it++) {                                               \
            int idx = tid + it * 128;                                                  \
            int row = idx >> 3, kq = (idx & 7) * 4;                                    \
            bool ok = (bm + row < M);                                                  \
            const float* src = A + (size_t)(ok ? bm + row : 0) * 512 + _k0 + kq;       \
            cp16(_ad + (unsigned)((row * 36 + kq) * 4), src, ok ? 16 : 0);             \
        }                                                                              \
        _Pragma("unroll")                                                              \
        for (int it = 0; it < 8; it++) {                                               \
            int idx = tid + it * 128;                                                  \
            int kr = idx >> 5, nq = (idx & 31) * 4;                                    \
            cp16(_bd + (unsigned)((kr * 136 + nq) * 4),                                \
                 Bm + (size_t)(_k0 + kr) * Nn + bn + nq, 16);                          \
        }                                                                              \
    } while (0)

    GEMM_ISSUE(0); CP_COMMIT();
    GEMM_ISSUE(1); CP_COMMIT();

    float acc[4][8][4];
#pragma unroll
    for (int mt = 0; mt < 4; mt++)
#pragma unroll
        for (int nt = 0; nt < 8; nt++)
#pragma unroll
            for (int e = 0; e < 4; e++) acc[mt][nt][e] = 0.f;

    for (int s = 0; s < 16; s++) {
        CP_WAIT1();
        __syncthreads();
        if (s + 2 < 16) GEMM_ISSUE(s + 2);
        CP_COMMIT();
        const float* Ab = As + (s % 3) * ASLAB;
        const float* Bb = Bs + (s % 3) * BSLAB;
#pragma unroll
        for (int kk = 0; kk < 4; kk++) {
            unsigned a[4][4];
#pragma unroll
            for (int mt = 0; mt < 4; mt++) {
                int r = wm * 64 + mt * 16 + gr;
                int cidx = kk * 8 + tg;
                a[mt][0] = __float_as_uint(Ab[r * 36 + cidx]);
                a[mt][1] = __float_as_uint(Ab[(r + 8) * 36 + cidx]);
                a[mt][2] = __float_as_uint(Ab[r * 36 + cidx + 4]);
                a[mt][3] = __float_as_uint(Ab[(r + 8) * 36 + cidx + 4]);
            }
            unsigned bf[8][2];
#pragma unroll
            for (int nt = 0; nt < 8; nt++) {
                int col = wn * 64 + nt * 8 + gr;
                bf[nt][0] = __float_as_uint(Bb[(kk * 8 + tg) * 136 + col]);
                bf[nt][1] = __float_as_uint(Bb[(kk * 8 + tg + 4) * 136 + col]);
            }
#pragma unroll
            for (int nt = 0; nt < 8; nt++)
#pragma unroll
                for (int mt = 0; mt < 4; mt++) mma8(acc[mt][nt], a[mt], bf[nt][0], bf[nt][1]);
        }
    }
#pragma unroll
    for (int mt = 0; mt < 4; mt++) {
        int r0 = bm + wm * 64 + mt * 16 + gr;
#pragma unroll
        for (int nt = 0; nt < 8; nt++) {
            int col = bn + wn * 64 + nt * 8 + 2 * tg;
            float bx = bias ? bias[col] : 0.f, by = bias ? bias[col + 1] : 0.f;
            float e0 = acc[mt][nt][0] + bx, e1 = acc[mt][nt][1] + by;
            float e2 = acc[mt][nt][2] + bx, e3 = acc[mt][nt][3] + by;
            if (rnd) { e0 = f2tff(e0); e1 = f2tff(e1); e2 = f2tff(e2); e3 = f2tff(e3); }
            if (r0 < M)     *(float2*)(C + (size_t)r0 * Nn + col)       = make_float2(e0, e1);
            if (r0 + 8 < M) *(float2*)(C + (size_t)(r0 + 8) * Nn + col) = make_float2(e2, e3);
        }
    }
#undef GEMM_ISSUE
}

__global__ void __launch_bounds__(128)
gemm_qkv_tc() {
    if (blockIdx.x < 8)
        gemm_tc_body(g_xm, g_wqk, g_qk, M_ROWS, 1024, nullptr, blockIdx.x, true);
    else
        gemm_tc_body(g_xm, g_wv, g_v, M_ROWS, 512, nullptr, blockIdx.x - 8, true);
}
__global__ void __launch_bounds__(128)
gemm_out_tc(const float* __restrict__ bias, float* __restrict__ out) {
    gemm_tc_body(g_ao, g_wo, out, M_ROWS, 512, bias, blockIdx.x, false);
}

// ================= Stage 3: flash attention, cp.async 2-stage K/V =================
#define KSTR 68
#define VSTR 72
#define PSTR 68
#define QROWS 96
#define KBUF (64 * KSTR)
#define VBUF (64 * VSTR)
#define NT_ ((N_ + 63) / 64)    // 10
#define FSMEM_FLOATS (2 * KBUF + 2 * VBUF + QROWS * PSTR + (2 * N_ - 1))

__global__ void __launch_bounds__(192, 2) flash_attn_tc(const float* __restrict__ rb) {
    extern __shared__ float sm[];
    float* Ks  = sm;
    float* Vs  = sm + 2 * KBUF;
    float* Ps  = sm + 2 * KBUF + 2 * VBUF;
    float* RBs = Ps + QROWS * PSTR;
    unsigned ks_u = s2u(Ks), vs_u = s2u(Vs);

    int b = blockIdx.z, h = blockIdx.y;
    int i0 = blockIdx.x * QROWS;
    int tid = threadIdx.x, lane = tid & 31, w = tid >> 5;
    int gr = lane >> 2, tg = lane & 3;

    const float* qb = g_qk + (size_t)b * N_ * 1024 + h * 64;
    const float* kb = qb + 512;
    const float* vb = g_v + (size_t)b * N_ * 512 + h * 64;

    for (int t = tid; t < 2 * N_ - 1; t += 192) RBs[t] = rb[t];

#define FL_ISSUE(jt)                                                                   \
    do {                                                                               \
        int _buf = (jt) & 1, _j0 = (jt) * 64;                                          \
        unsigned _kd = ks_u + (unsigned)(_buf * KBUF * 4);                             \
        unsigned _vd = vs_u + (unsigned)(_buf * VBUF * 4);                             \
        for (int idx = tid; idx < 1024; idx += 192) {                                  \
            int row = idx >> 4, cq = (idx & 15) * 4;                                   \
            int j = _j0 + row;                                                         \
            bool ok = (j < N_);                                                        \
            int js = ok ? j : 0;                                                       \
            cp16(_kd + (unsigned)((row * KSTR + cq) * 4),                              \
                 kb + (size_t)js * 1024 + cq, ok ? 16 : 0);                            \
            cp16(_vd + (unsigned)((row * VSTR + cq) * 4),                              \
                 vb + (size_t)js * 512 + cq, ok ? 16 : 0);                             \
        }                                                                              \
    } while (0)

    unsigned qa[8][4];
    int rlo = i0 + w * 16 + gr;
    int rhi = rlo + 8;
#pragma unroll
    for (int kk = 0; kk < 8; kk++) {
        int c0 = kk * 8 + tg;
        float v0 = (rlo < N_) ? 0.125f * qb[(size_t)rlo * 1024 + c0]     : 0.f;
        float v1 = (rhi < N_) ? 0.125f * qb[(size_t)rhi * 1024 + c0]     : 0.f;
        float v2 = (rlo < N_) ? 0.125f * qb[(size_t)rlo * 1024 + c0 + 4] : 0.f;
        float v3 = (rhi < N_) ? 0.125f * qb[(size_t)rhi * 1024 + c0 + 4] : 0.f;
        qa[kk][0] = __float_as_uint(v0); qa[kk][1] = __float_as_uint(v1);
        qa[kk][2] = __float_as_uint(v2); qa[kk][3] = __float_as_uint(v3);
    }

    FL_ISSUE(0); CP_COMMIT();

    float o[8][4], ob[8][4];
#pragma unroll
    for (int nt = 0; nt < 8; nt++)
#pragma unroll
        for (int e = 0; e < 4; e++) { o[nt][e] = 0.f; ob[nt][e] = 0.f; }
    float mlo = -1e30f, mhi = -1e30f, zlo = 0.f, zhi = 0.f;

    for (int jt = 0; jt < NT_; jt++) {
        int j0 = jt * 64;
        bool full = (j0 + 64 <= N_);
        __syncthreads();
        if (jt + 1 < NT_) FL_ISSUE(jt + 1);
        CP_COMMIT();
        CP_WAIT1();
        __syncthreads();
        const float* Ksb = Ks + (jt & 1) * KBUF;
        const float* Vsb = Vs + (jt & 1) * VBUF;

        float s[8][4];
#pragma unroll
        for (int nt = 0; nt < 8; nt++) {
#pragma unroll
            for (int e = 0; e < 4; e++) s[nt][e] = 0.f;
#pragma unroll
            for (int kk = 0; kk < 8; kk++) {
                unsigned b0 = __float_as_uint(Ksb[(nt * 8 + gr) * KSTR + kk * 8 + tg]);
                unsigned b1 = __float_as_uint(Ksb[(nt * 8 + gr) * KSTR + kk * 8 + tg + 4]);
                mma8(s[nt], qa[kk], b0, b1);
            }
        }

        float tlo = -1e30f, thi = -1e30f;
#pragma unroll
        for (int nt = 0; nt < 8; nt++) {
            int col = j0 + nt * 8 + 2 * tg;
            if (full || col < N_)     { tlo = fmaxf(tlo, s[nt][0]); thi = fmaxf(thi, s[nt][2]); }
            if (full || col + 1 < N_) { tlo = fmaxf(tlo, s[nt][1]); thi = fmaxf(thi, s[nt][3]); }
        }
#pragma unroll
        for (int off = 1; off <= 2; off <<= 1) {
            tlo = fmaxf(tlo, __shfl_xor_sync(0xffffffffu, tlo, off));
            thi = fmaxf(thi, __shfl_xor_sync(0xffffffffu, thi, off));
        }
        float mlon = fmaxf(mlo, tlo), mhin = fmaxf(mhi, thi);
        float sclo = __expf(mlo - mlon), schi = __expf(mhi - mhin);
        float psl = 0.f, psh = 0.f;
        int prow_lo = (w * 16 + gr) * PSTR;
        int prow_hi = (w * 16 + gr + 8) * PSTR;
#pragma unroll
        for (int nt = 0; nt < 8; nt++) {
            int col = j0 + nt * 8 + 2 * tg;
            float p0 = (full || col     < N_) ? __expf(s[nt][0] - mlon) : 0.f;
            float p1 = (full || col + 1 < N_) ? __expf(s[nt][1] - mlon) : 0.f;
            float p2 = (full || col     < N_) ? __expf(s[nt][2] - mhin) : 0.f;
            float p3 = (full || col + 1 < N_) ? __expf(s[nt][3] - mhin) : 0.f;
            psl += p0 + p1; psh += p2 + p3;
            o[nt][0] *= sclo; o[nt][1] *= sclo;
            o[nt][2] *= schi; o[nt][3] *= schi;
            *(float2*)(Ps + prow_lo + nt * 8 + 2 * tg) = make_float2(f2tff(p0), f2tff(p1));
            *(float2*)(Ps + prow_hi + nt * 8 + 2 * tg) = make_float2(f2tff(p2), f2tff(p3));
        }
#pragma unroll
        for (int off = 1; off <= 2; off <<= 1) {
            psl += __shfl_xor_sync(0xffffffffu, psl, off);
            psh += __shfl_xor_sync(0xffffffffu, psh, off);
        }
        zlo = zlo * sclo + psl;  zhi = zhi * schi + psh;
        mlo = mlon;  mhi = mhin;
        __syncwarp();

#pragma unroll
        for (int kk = 0; kk < 8; kk++) {
            unsigned pa[4], ba[4];
            int pc = kk * 8 + tg;
            pa[0] = __float_as_uint(Ps[prow_lo + pc]);
            pa[1] = __float_as_uint(Ps[prow_hi + pc]);
            pa[2] = __float_as_uint(Ps[prow_lo + pc + 4]);
            pa[3] = __float_as_uint(Ps[prow_hi + pc + 4]);
            int jlo = j0 + kk * 8 + tg, jhi = jlo + 4;
            float b00 = (rlo < N_ && jlo < N_) ? RBs[576 + jlo - rlo] : 0.f;
            float b01 = (rhi < N_ && jlo < N_) ? RBs[576 + jlo - rhi] : 0.f;
            float b02 = (rlo < N_ && jhi < N_) ? RBs[576 + jhi - rlo] : 0.f;
            float b03 = (rhi < N_ && jhi < N_) ? RBs[576 + jhi - rhi] : 0.f;
            ba[0] = f2tf(b00); ba[1] = f2tf(b01); ba[2] = f2tf(b02); ba[3] = f2tf(b03);
#pragma unroll
            for (int nt = 0; nt < 8; nt++) {
                unsigned v0 = __float_as_uint(Vsb[(kk * 8 + tg) * VSTR + nt * 8 + gr]);
                unsigned v1 = __float_as_uint(Vsb[(kk * 8 + tg + 4) * VSTR + nt * 8 + gr]);
                mma8(o[nt],  pa, v0, v1);
                mma8(ob[nt], ba, v0, v1);
            }
        }
        __syncwarp();
    }

    float izlo = 1.f / zlo, izhi = 1.f / zhi;
#pragma unroll
    for (int nt = 0; nt < 8; nt++) {
        int col = h * 64 + nt * 8 + 2 * tg;
        if (rlo < N_) {
            float2 v = make_float2(f2tff(o[nt][0] * izlo + ob[nt][0]),
                                   f2tff(o[nt][1] * izlo + ob[nt][1]));
            *(float2*)(g_ao + ((size_t)b * N_ + rlo) * 512 + col) = v;
        }
        if (rhi < N_) {
            float2 v = make_float2(f2tff(o[nt][2] * izhi + ob[nt][2]),
                                   f2tff(o[nt][3] * izhi + ob[nt][3]));
            *(float2*)(g_ao + ((size_t)b * N_ + rhi) * 512 + col) = v;
        }
    }
#undef FL_ISSUE
}

// ================= launch =================
extern "C" void kernel_launch(void* const* d_in, const int* in_sizes, int n_in,
                              void* d_out, int out_size) {
    const float* x         = (const float*)d_in[0];
    const float* W_qk      = (const float*)d_in[1];
    const float* W_v       = (const float*)d_in[2];
    const float* W_out     = (const float*)d_in[3];
    const float* b_out     = (const float*)d_in[4];
    const float* rel_bias  = (const float*)d_in[5];
    const float* ema_delta = (const float*)d_in[6];
    const float* ema_alpha = (const float*)d_in[7];
    const float* ema_beta  = (const float*)d_in[8];
    const float* ema_gamma = (const float*)d_in[9];
    const float* ema_omega = (const float*)d_in[10];
    float* out = (float*)d_out;

    static int attr_set = 0;
    if (!attr_set) {
        cudaFuncSetAttribute(gemm_qkv_tc, cudaFuncAttributeMaxDynamicSharedMemorySize, GSMEM_BYTES);
        cudaFuncSetAttribute(gemm_out_tc, cudaFuncAttributeMaxDynamicSharedMemorySize, GSMEM_BYTES);
        cudaFuncSetAttribute(flash_attn_tc, cudaFuncAttributeMaxDynamicSharedMemorySize,
                             FSMEM_FLOATS * (int)sizeof(float));
        attr_set = 1;
    }

    coef_kernel<<<(2 * DIM_ * NDIM_ + 255) / 256, 256>>>(ema_delta, ema_alpha, ema_beta, ema_gamma);
    wcvt_kernel<<<(512 * 1024 + 255) / 256, 256>>>(W_qk, W_v, W_out);
    ema1_kernel<<<dim3(DIM_ / 128, CH_, B_), 128>>>(x);
    ema_scan_kernel<<<dim3(DIM_ / 128, NDIM_, B_), 128>>>();
    ema2_kernel<<<dim3(DIM_ / 128, CH_, B_), 128>>>(x, ema_omega);

    gemm_qkv_tc<<<dim3(12, 145), 128, GSMEM_BYTES>>>();

    flash_attn_tc<<<dim3((N_ + QROWS - 1) / QROWS, HEADS_, B_), 192,
                    FSMEM_FLOATS * sizeof(float)>>>(rel_bias);

    gemm_out_tc<<<dim3(4, 145), 128, GSMEM_BYTES>>>(b_out, out);
}

// round 7
// speedup vs baseline: 1.0499x; 1.0499x over previous
#include <cuda_runtime.h>

#define B_     32
#define N_     577
#define L_     576
#define DIM_   512
#define HEADS_ 8
#define DH_    64
#define NDIM_  16
#define INNER_ 512
#define M_ROWS (B_ * N_)   // 18464
#define ECH 16             // EMA chunks
#define ECL 36             // EMA chunk length (16*36 = 576)

// -------- scratch (device globals) --------
__device__ float g_xm[(size_t)B_ * N_ * DIM_];
__device__ float g_qk[(size_t)B_ * N_ * 2 * INNER_];
__device__ float g_v [(size_t)B_ * N_ * INNER_];
__device__ float g_ao[(size_t)B_ * N_ * INNER_];
__device__ float g_cq[NDIM_][2 * DIM_];
__device__ float g_cc[NDIM_][2 * DIM_];
__device__ float g_wqk[512 * 1024];
__device__ float g_wv [512 * 512];
__device__ float g_wo [512 * 512];

// ---------------- helpers ----------------
__device__ __forceinline__ unsigned f2tf(float x) {
    unsigned u;
    asm("cvt.rna.tf32.f32 %0, %1;" : "=r"(u) : "f"(x));
    return u;
}
__device__ __forceinline__ float f2tff(float x) { return __uint_as_float(f2tf(x)); }

__device__ __forceinline__ void mma8(float* c, const unsigned* a, unsigned b0, unsigned b1) {
    asm volatile(
        "mma.sync.aligned.m16n8k8.row.col.f32.tf32.tf32.f32 "
        "{%0,%1,%2,%3},{%4,%5,%6,%7},{%8,%9},{%0,%1,%2,%3};"
        : "+f"(c[0]), "+f"(c[1]), "+f"(c[2]), "+f"(c[3])
        : "r"(a[0]), "r"(a[1]), "r"(a[2]), "r"(a[3]), "r"(b0), "r"(b1));
}

__device__ __forceinline__ unsigned s2u(const void* p) {
    return (unsigned)__cvta_generic_to_shared(p);
}
__device__ __forceinline__ void cp16(unsigned dst, const void* src, int srcsz) {
    asm volatile("cp.async.cg.shared.global [%0], [%1], 16, %2;"
                 :: "r"(dst), "l"(src), "r"(srcsz));
}
#define CP_COMMIT() asm volatile("cp.async.commit_group;")
#define CP_WAIT1()  asm volatile("cp.async.wait_group 1;")

__device__ __forceinline__ float pow36f(float q) {
    float q2 = q * q, q4 = q2 * q2, q8 = q4 * q4, q16 = q8 * q8, q32 = q16 * q16;
    return q32 * q4;
}

// ================= Stage 0: EMA coefficients + weight rounding =================
__global__ void coef_kernel(const float* __restrict__ delta, const float* __restrict__ alpha,
                            const float* __restrict__ beta,  const float* __restrict__ gamma) {
    int idx = blockIdx.x * blockDim.x + threadIdx.x;
    if (idx >= 2 * DIM_ * NDIM_) return;
    int d = idx / NDIM_;
    int n = idx % NDIM_;
    float p  = 1.f / (1.f + expf(-delta[idx]));
    float sa = 1.f / (1.f + expf(-alpha[idx]));
    g_cq[n][d] = 1.f - p * sa;
    g_cc[n][d] = p * beta[idx] * gamma[idx] * 0.25f;
}

__global__ void wcvt_kernel(const float* __restrict__ wqk, const float* __restrict__ wv,
                            const float* __restrict__ wo) {
    int i = blockIdx.x * 256 + threadIdx.x;
    if (i < 512 * 1024) g_wqk[i] = f2tff(wqk[i]);
    if (i < 512 * 512) {
        g_wv[i] = f2tff(wv[i]);
        g_wo[i] = f2tff(wo[i]);
    }
}

// ================= Stage 1: fused bidirectional EMA =================
// CTA = (b, block of 16 channels); thread (c, dl): chunk c, channel dl.
// smem: Sf/Sb chunk-end states [c][n][17], Ys fwd partial y [tl][c*17+dl].
#define ESM_STATE (ECH * NDIM_ * 17)          // 4352 floats
#define ESM_Y     (ECL * ECH * 17)            // 9792 floats
#define ESM_TOTAL (2 * ESM_STATE + ESM_Y)     // 18496 floats = 73984 B

__global__ void __launch_bounds__(256, 2) ema_fused(const float* __restrict__ x,
                                                    const float* __restrict__ omega) {
    extern __shared__ float es[];
    float* Sf = es;
    float* Sb = es + ESM_STATE;
    float* Ys = es + 2 * ESM_STATE;

    int tid = threadIdx.x;
    int c = tid >> 4, dl = tid & 15;
    int d = blockIdx.x * 16 + dl;
    int b = blockIdx.z;
    const float* xb = x    + (size_t)b * N_ * DIM_ + d;
    float*       yb = g_xm + (size_t)b * N_ * DIM_ + d;
    int t0 = c * ECL;

    if (tid < 16) yb[0] = f2tff(xb[0]);   // cls token passthrough (rounded)

    float q[NDIM_], q2[NDIM_], s[NDIM_];
    // ---- pass 1 forward: chunk-end state only (no y) ----
#pragma unroll
    for (int n = 0; n < NDIM_; n++) { q[n] = g_cq[n][d]; s[n] = 0.f; }
#pragma unroll 4
    for (int tl = 0; tl < ECL; tl++) {
        float xv = xb[(size_t)(t0 + tl + 1) * DIM_];
#pragma unroll
        for (int n = 0; n < NDIM_; n++) s[n] = q[n] * s[n] + xv;
    }
#pragma unroll
    for (int n = 0; n < NDIM_; n++) Sf[(c * NDIM_ + n) * 17 + dl] = s[n];

    // ---- pass 1 backward ----
#pragma unroll
    for (int n = 0; n < NDIM_; n++) { q2[n] = g_cq[n][d + DIM_]; s[n] = 0.f; }
#pragma unroll 4
    for (int tl = ECL - 1; tl >= 0; tl--) {
        float xv = xb[(size_t)(t0 + tl + 1) * DIM_];
#pragma unroll
        for (int n = 0; n < NDIM_; n++) s[n] = q2[n] * s[n] + xv;
    }
#pragma unroll
    for (int n = 0; n < NDIM_; n++) Sb[(c * NDIM_ + n) * 17 + dl] = s[n];
    __syncthreads();

    // ---- incoming fwd state (prefix over chunk states) + pass 2 fwd ----
    float cc[NDIM_];
#pragma unroll
    for (int n = 0; n < NDIM_; n++) {
        float qp = pow36f(q[n]);
        float Sin = 0.f;
        for (int cp = 0; cp < c; cp++)
            Sin = qp * Sin + Sf[(cp * NDIM_ + n) * 17 + dl];
        s[n] = Sin;
        cc[n] = g_cc[n][d];
    }
#pragma unroll 4
    for (int tl = 0; tl < ECL; tl++) {
        float xv = xb[(size_t)(t0 + tl + 1) * DIM_];
        float a[4] = {0.f, 0.f, 0.f, 0.f};
#pragma unroll
        for (int n = 0; n < NDIM_; n++) { s[n] = q[n] * s[n] + xv; a[n >> 2] += cc[n] * s[n]; }
        Ys[tl * (ECH * 17) + c * 17 + dl] = (a[0] + a[1]) + (a[2] + a[3]);
    }

    // ---- incoming bwd state (suffix) + pass 2 bwd + silu + single store ----
#pragma unroll
    for (int n = 0; n < NDIM_; n++) {
        float qp = pow36f(q2[n]);
        float Sin = 0.f;
        for (int cp = ECH - 1; cp > c; cp--)
            Sin = qp * Sin + Sb[(cp * NDIM_ + n) * 17 + dl];
        s[n] = Sin;
        cc[n] = g_cc[n][d + DIM_];
    }
    float om = omega[d];
#pragma unroll 4
    for (int tl = ECL - 1; tl >= 0; tl--) {
        float xv = xb[(size_t)(t0 + tl + 1) * DIM_];
        float a[4] = {0.f, 0.f, 0.f, 0.f};
#pragma unroll
        for (int n = 0; n < NDIM_; n++) { s[n] = q2[n] * s[n] + xv; a[n >> 2] += cc[n] * s[n]; }
        float u = Ys[tl * (ECH * 17) + c * 17 + dl]
                + ((a[0] + a[1]) + (a[2] + a[3])) + xv * om;
        yb[(size_t)(t0 + tl + 1) * DIM_] = f2tff(u / (1.f + __expf(-u)));
    }
}

// ================= tf32 GEMM: 128x128 CTA, 4 warps 64x64, cp.async 3-stage =================
#define ASLAB (128 * 36)
#define BSLAB (32 * 136)
#define GSMEM_BYTES (3 * (ASLAB + BSLAB) * 4)

__device__ __forceinline__ void gemm_tc_body(const float* __restrict__ A, const float* __restrict__ Bm,
                                             float* __restrict__ C, int M, int Nn,
                                             const float* __restrict__ bias, int bnb, bool rnd) {
    extern __shared__ float gsm[];
    float* As = gsm;
    float* Bs = gsm + 3 * ASLAB;
    unsigned as_u = s2u(As), bs_u = s2u(Bs);

    int tid = threadIdx.x, lane = tid & 31, w = tid >> 5;
    int gr = lane >> 2, tg = lane & 3;
    int wm = w & 1, wn = w >> 1;
    int bm = blockIdx.y * 128, bn = bnb * 128;

#define GEMM_ISSUE(s)                                                                  \
    do {                                                                               \
        int _buf = (s) % 3, _k0 = (s) * 32;                                            \
        unsigned _ad = as_u + (unsigned)(_buf * ASLAB * 4);                            \
        unsigned _bd = bs_u + (unsigned)(_buf * BSLAB * 4);                            \
        _Pragma("unroll")                                                              \
        for (int it = 0; it < 8; it++) {                                               \
            int idx = tid + it * 128;                                                  \
            int row = idx >> 3, kq = (idx & 7) * 4;                                    \
            bool ok = (bm + row < M);                                                  \
            const float* src = A + (size_t)(ok ? bm + row : 0) * 512 + _k0 + kq;       \
            cp16(_ad + (unsigned)((row * 36 + kq) * 4), src, ok ? 16 : 0);             \
        }                                                                              \
        _Pragma("unroll")                                                              \
        for (int it = 0; it < 8; it++) {                                               \
            int idx = tid + it * 128;                                                  \
            int kr = idx >> 5, nq = (idx & 31) * 4;                                    \
            cp16(_bd + (unsigned)((kr * 136 + nq) * 4),                                \
                 Bm + (size_t)(_k0 + kr) * Nn + bn + nq, 16);                          \
        }                                                                              \
    } while (0)

    GEMM_ISSUE(0); CP_COMMIT();
    GEMM_ISSUE(1); CP_COMMIT();

    float acc[4][8][4];
#pragma unroll
    for (int mt = 0; mt < 4; mt++)
#pragma unroll
        for (int nt = 0; nt < 8; nt++)
#pragma unroll
            for (int e = 0; e < 4; e++) acc[mt][nt][e] = 0.f;

    for (int s = 0; s < 16; s++) {
        CP_WAIT1();
        __syncthreads();
        if (s + 2 < 16) GEMM_ISSUE(s + 2);
        CP_COMMIT();
        const float* Ab = As + (s % 3) * ASLAB;
        const float* Bb = Bs + (s % 3) * BSLAB;
#pragma unroll
        for (int kk = 0; kk < 4; kk++) {
            unsigned a[4][4];
#pragma unroll
            for (int mt = 0; mt < 4; mt++) {
                int r = wm * 64 + mt * 16 + gr;
                int cidx = kk * 8 + tg;
                a[mt][0] = __float_as_uint(Ab[r * 36 + cidx]);
                a[mt][1] = __float_as_uint(Ab[(r + 8) * 36 + cidx]);
                a[mt][2] = __float_as_uint(Ab[r * 36 + cidx + 4]);
                a[mt][3] = __float_as_uint(Ab[(r + 8) * 36 + cidx + 4]);
            }
            unsigned bf[8][2];
#pragma unroll
            for (int nt = 0; nt < 8; nt++) {
                int col = wn * 64 + nt * 8 + gr;
                bf[nt][0] = __float_as_uint(Bb[(kk * 8 + tg) * 136 + col]);
                bf[nt][1] = __float_as_uint(Bb[(kk * 8 + tg + 4) * 136 + col]);
            }
#pragma unroll
            for (int nt = 0; nt < 8; nt++)
#pragma unroll
                for (int mt = 0; mt < 4; mt++) mma8(acc[mt][nt], a[mt], bf[nt][0], bf[nt][1]);
        }
    }
#pragma unroll
    for (int mt = 0; mt < 4; mt++) {
        int r0 = bm + wm * 64 + mt * 16 + gr;
#pragma unroll
        for (int nt = 0; nt < 8; nt++) {
            int col = bn + wn * 64 + nt * 8 + 2 * tg;
            float bx = bias ? bias[col] : 0.f, by = bias ? bias[col + 1] : 0.f;
            float e0 = acc[mt][nt][0] + bx, e1 = acc[mt][nt][1] + by;
            float e2 = acc[mt][nt][2] + bx, e3 = acc[mt][nt][3] + by;
            if (rnd) { e0 = f2tff(e0); e1 = f2tff(e1); e2 = f2tff(e2); e3 = f2tff(e3); }
            if (r0 < M)     *(float2*)(C + (size_t)r0 * Nn + col)       = make_float2(e0, e1);
            if (r0 + 8 < M) *(float2*)(C + (size_t)(r0 + 8) * Nn + col) = make_float2(e2, e3);
        }
    }
#undef GEMM_ISSUE
}

__global__ void __launch_bounds__(128)
gemm_qkv_tc() {
    if (blockIdx.x < 8)
        gemm_tc_body(g_xm, g_wqk, g_qk, M_ROWS, 1024, nullptr, blockIdx.x, true);
    else
        gemm_tc_body(g_xm, g_wv, g_v, M_ROWS, 512, nullptr, blockIdx.x - 8, true);
}
__global__ void __launch_bounds__(128)
gemm_out_tc(const float* __restrict__ bias, float* __restrict__ out) {
    gemm_tc_body(g_ao, g_wo, out, M_ROWS, 512, bias, blockIdx.x, false);
}

// ================= Stage 3: flash attention, cp.async 2-stage K/V =================
#define KSTR 68
#define VSTR 72
#define PSTR 68
#define QROWS 96
#define KBUF (64 * KSTR)
#define VBUF (64 * VSTR)
#define NT_ ((N_ + 63) / 64)    // 10
#define FSMEM_FLOATS (2 * KBUF + 2 * VBUF + QROWS * PSTR + (2 * N_ - 1))

__global__ void __launch_bounds__(192, 2) flash_attn_tc(const float* __restrict__ rb) {
    extern __shared__ float sm[];
    float* Ks  = sm;
    float* Vs  = sm + 2 * KBUF;
    float* Ps  = sm + 2 * KBUF + 2 * VBUF;
    float* RBs = Ps + QROWS * PSTR;
    unsigned ks_u = s2u(Ks), vs_u = s2u(Vs);

    int b = blockIdx.z, h = blockIdx.y;
    int i0 = blockIdx.x * QROWS;
    int tid = threadIdx.x, lane = tid & 31, w = tid >> 5;
    int gr = lane >> 2, tg = lane & 3;

    const float* qb = g_qk + (size_t)b * N_ * 1024 + h * 64;
    const float* kb = qb + 512;
    const float* vb = g_v + (size_t)b * N_ * 512 + h * 64;

    for (int t = tid; t < 2 * N_ - 1; t += 192) RBs[t] = rb[t];

#define FL_ISSUE(jt)                                                                   \
    do {                                                                               \
        int _buf = (jt) & 1, _j0 = (jt) * 64;                                          \
        unsigned _kd = ks_u + (unsigned)(_buf * KBUF * 4);                             \
        unsigned _vd = vs_u + (unsigned)(_buf * VBUF * 4);                             \
        for (int idx = tid; idx < 1024; idx += 192) {                                  \
            int row = idx >> 4, cq = (idx & 15) * 4;                                   \
            int j = _j0 + row;                                                         \
            bool ok = (j < N_);                                                        \
            int js = ok ? j : 0;                                                       \
            cp16(_kd + (unsigned)((row * KSTR + cq) * 4),                              \
                 kb + (size_t)js * 1024 + cq, ok ? 16 : 0);                            \
            cp16(_vd + (unsigned)((row * VSTR + cq) * 4),                              \
                 vb + (size_t)js * 512 + cq, ok ? 16 : 0);                             \
        }                                                                              \
    } while (0)

    unsigned qa[8][4];
    int rlo = i0 + w * 16 + gr;
    int rhi = rlo + 8;
#pragma unroll
    for (int kk = 0; kk < 8; kk++) {
        int c0 = kk * 8 + tg;
        float v0 = (rlo < N_) ? 0.125f * qb[(size_t)rlo * 1024 + c0]     : 0.f;
        float v1 = (rhi < N_) ? 0.125f * qb[(size_t)rhi * 1024 + c0]     : 0.f;
        float v2 = (rlo < N_) ? 0.125f * qb[(size_t)rlo * 1024 + c0 + 4] : 0.f;
        float v3 = (rhi < N_) ? 0.125f * qb[(size_t)rhi * 1024 + c0 + 4] : 0.f;
        qa[kk][0] = __float_as_uint(v0); qa[kk][1] = __float_as_uint(v1);
        qa[kk][2] = __float_as_uint(v2); qa[kk][3] = __float_as_uint(v3);
    }

    FL_ISSUE(0); CP_COMMIT();

    float o[8][4], ob[8][4];
#pragma unroll
    for (int nt = 0; nt < 8; nt++)
#pragma unroll
        for (int e = 0; e < 4; e++) { o[nt][e] = 0.f; ob[nt][e] = 0.f; }
    float mlo = -1e30f, mhi = -1e30f, zlo = 0.f, zhi = 0.f;

    for (int jt = 0; jt < NT_; jt++) {
        int j0 = jt * 64;
        bool full = (j0 + 64 <= N_);
        __syncthreads();
        if (jt + 1 < NT_) FL_ISSUE(jt + 1);
        CP_COMMIT();
        CP_WAIT1();
        __syncthreads();
        const float* Ksb = Ks + (jt & 1) * KBUF;
        const float* Vsb = Vs + (jt & 1) * VBUF;

        float s[8][4];
#pragma unroll
        for (int nt = 0; nt < 8; nt++) {
#pragma unroll
            for (int e = 0; e < 4; e++) s[nt][e] = 0.f;
#pragma unroll
            for (int kk = 0; kk < 8; kk++) {
                unsigned b0 = __float_as_uint(Ksb[(nt * 8 + gr) * KSTR + kk * 8 + tg]);
                unsigned b1 = __float_as_uint(Ksb[(nt * 8 + gr) * KSTR + kk * 8 + tg + 4]);
                mma8(s[nt], qa[kk], b0, b1);
            }
        }

        float tlo = -1e30f, thi = -1e30f;
#pragma unroll
        for (int nt = 0; nt < 8; nt++) {
            int col = j0 + nt * 8 + 2 * tg;
            if (full || col < N_)     { tlo = fmaxf(tlo, s[nt][0]); thi = fmaxf(thi, s[nt][2]); }
            if (full || col + 1 < N_) { tlo = fmaxf(tlo, s[nt][1]); thi = fmaxf(thi, s[nt][3]); }
        }
#pragma unroll
        for (int off = 1; off <= 2; off <<= 1) {
            tlo = fmaxf(tlo, __shfl_xor_sync(0xffffffffu, tlo, off));
            thi = fmaxf(thi, __shfl_xor_sync(0xffffffffu, thi, off));
        }
        float mlon = fmaxf(mlo, tlo), mhin = fmaxf(mhi, thi);
        float sclo = __expf(mlo - mlon), schi = __expf(mhi - mhin);
        float psl = 0.f, psh = 0.f;
        int prow_lo = (w * 16 + gr) * PSTR;
        int prow_hi = (w * 16 + gr + 8) * PSTR;
#pragma unroll
        for (int nt = 0; nt < 8; nt++) {
            int col = j0 + nt * 8 + 2 * tg;
            float p0 = (full || col     < N_) ? __expf(s[nt][0] - mlon) : 0.f;
            float p1 = (full || col + 1 < N_) ? __expf(s[nt][1] - mlon) : 0.f;
            float p2 = (full || col     < N_) ? __expf(s[nt][2] - mhin) : 0.f;
            float p3 = (full || col + 1 < N_) ? __expf(s[nt][3] - mhin) : 0.f;
            psl += p0 + p1; psh += p2 + p3;
            o[nt][0] *= sclo; o[nt][1] *= sclo;
            o[nt][2] *= schi; o[nt][3] *= schi;
            *(float2*)(Ps + prow_lo + nt * 8 + 2 * tg) = make_float2(f2tff(p0), f2tff(p1));
            *(float2*)(Ps + prow_hi + nt * 8 + 2 * tg) = make_float2(f2tff(p2), f2tff(p3));
        }
#pragma unroll
        for (int off = 1; off <= 2; off <<= 1) {
            psl += __shfl_xor_sync(0xffffffffu, psl, off);
            psh += __shfl_xor_sync(0xffffffffu, psh, off);
        }
        zlo = zlo * sclo + psl;  zhi = zhi * schi + psh;
        mlo = mlon;  mhi = mhin;
        __syncwarp();

#pragma unroll
        for (int kk = 0; kk < 8; kk++) {
            unsigned pa[4], ba[4];
            int pc = kk * 8 + tg;
            pa[0] = __float_as_uint(Ps[prow_lo + pc]);
            pa[1] = __float_as_uint(Ps[prow_hi + pc]);
            pa[2] = __float_as_uint(Ps[prow_lo + pc + 4]);
            pa[3] = __float_as_uint(Ps[prow_hi + pc + 4]);
            int jlo = j0 + kk * 8 + tg, jhi = jlo + 4;
            float b00 = (rlo < N_ && jlo < N_) ? RBs[576 + jlo - rlo] : 0.f;
            float b01 = (rhi < N_ && jlo < N_) ? RBs[576 + jlo - rhi] : 0.f;
            float b02 = (rlo < N_ && jhi < N_) ? RBs[576 + jhi - rlo] : 0.f;
            float b03 = (rhi < N_ && jhi < N_) ? RBs[576 + jhi - rhi] : 0.f;
            ba[0] = f2tf(b00); ba[1] = f2tf(b01); ba[2] = f2tf(b02); ba[3] = f2tf(b03);
#pragma unroll
            for (int nt = 0; nt < 8; nt++) {
                unsigned v0 = __float_as_uint(Vsb[(kk * 8 + tg) * VSTR + nt * 8 + gr]);
                unsigned v1 = __float_as_uint(Vsb[(kk * 8 + tg + 4) * VSTR + nt * 8 + gr]);
                mma8(o[nt],  pa, v0, v1);
                mma8(ob[nt], ba, v0, v1);
            }
        }
        __syncwarp();
    }

    float izlo = 1.f / zlo, izhi = 1.f / zhi;
#pragma unroll
    for (int nt = 0; nt < 8; nt++) {
        int col = h * 64 + nt * 8 + 2 * tg;
        if (rlo < N_) {
            float2 v = make_float2(f2tff(o[nt][0] * izlo + ob[nt][0]),
                                   f2tff(o[nt][1] * izlo + ob[nt][1]));
            *(float2*)(g_ao + ((size_t)b * N_ + rlo) * 512 + col) = v;
        }
        if (rhi < N_) {
            float2 v = make_float2(f2tff(o[nt][2] * izhi + ob[nt][2]),
                                   f2tff(o[nt][3] * izhi + ob[nt][3]));
            *(float2*)(g_ao + ((size_t)b * N_ + rhi) * 512 + col) = v;
        }
    }
#undef FL_ISSUE
}

// ================= launch =================
extern "C" void kernel_launch(void* const* d_in, const int* in_sizes, int n_in,
                              void* d_out, int out_size) {
    const float* x         = (const float*)d_in[0];
    const float* W_qk      = (const float*)d_in[1];
    const float* W_v       = (const float*)d_in[2];
    const float* W_out     = (const float*)d_in[3];
    const float* b_out     = (const float*)d_in[4];
    const float* rel_bias  = (const float*)d_in[5];
    const float* ema_delta = (const float*)d_in[6];
    const float* ema_alpha = (const float*)d_in[7];
    const float* ema_beta  = (const float*)d_in[8];
    const float* ema_gamma = (const float*)d_in[9];
    const float* ema_omega = (const float*)d_in[10];
    float* out = (float*)d_out;

    static int attr_set = 0;
    if (!attr_set) {
        cudaFuncSetAttribute(ema_fused, cudaFuncAttributeMaxDynamicSharedMemorySize,
                             ESM_TOTAL * (int)sizeof(float));
        cudaFuncSetAttribute(gemm_qkv_tc, cudaFuncAttributeMaxDynamicSharedMemorySize, GSMEM_BYTES);
        cudaFuncSetAttribute(gemm_out_tc, cudaFuncAttributeMaxDynamicSharedMemorySize, GSMEM_BYTES);
        cudaFuncSetAttribute(flash_attn_tc, cudaFuncAttributeMaxDynamicSharedMemorySize,
                             FSMEM_FLOATS * (int)sizeof(float));
        attr_set = 1;
    }

    coef_kernel<<<(2 * DIM_ * NDIM_ + 255) / 256, 256>>>(ema_delta, ema_alpha, ema_beta, ema_gamma);
    wcvt_kernel<<<(512 * 1024 + 255) / 256, 256>>>(W_qk, W_v, W_out);
    ema_fused<<<dim3(DIM_ / 16, 1, B_), 256, ESM_TOTAL * sizeof(float)>>>(x, ema_omega);

    gemm_qkv_tc<<<dim3(12, 145), 128, GSMEM_BYTES>>>();

    flash_attn_tc<<<dim3((N_ + QROWS - 1) / QROWS, HEADS_, B_), 192,
                    FSMEM_FLOATS * sizeof(float)>>>(rel_bias);

    gemm_out_tc<<<dim3(4, 145), 128, GSMEM_BYTES>>>(b_out, out);
}

// round 8
// speedup vs baseline: 1.0521x; 1.0021x over previous
#include <cuda_runtime.h>

#define B_     32
#define N_     577
#define L_     576
#define DIM_   512
#define HEADS_ 8
#define DH_    64
#define NDIM_  16
#define INNER_ 512
#define M_ROWS (B_ * N_)   // 18464
#define ECH 16             // EMA chunks
#define ECL 36             // EMA chunk length (16*36 = 576)

// -------- scratch (device globals) --------
__device__ float g_xm[(size_t)B_ * N_ * DIM_];
__device__ float g_qk[(size_t)B_ * N_ * 2 * INNER_];
__device__ float g_v [(size_t)B_ * N_ * INNER_];
__device__ float g_ao[(size_t)B_ * N_ * INNER_];
__device__ float g_cq[NDIM_][2 * DIM_];
__device__ float g_cc[NDIM_][2 * DIM_];
__device__ float g_wqk[512 * 1024];
__device__ float g_wv [512 * 512];
__device__ float g_wo [512 * 512];

// ---------------- helpers ----------------
__device__ __forceinline__ unsigned f2tf(float x) {
    unsigned u;
    asm("cvt.rna.tf32.f32 %0, %1;" : "=r"(u) : "f"(x));
    return u;
}
__device__ __forceinline__ float f2tff(float x) { return __uint_as_float(f2tf(x)); }

__device__ __forceinline__ void mma8(float* c, const unsigned* a, unsigned b0, unsigned b1) {
    asm volatile(
        "mma.sync.aligned.m16n8k8.row.col.f32.tf32.tf32.f32 "
        "{%0,%1,%2,%3},{%4,%5,%6,%7},{%8,%9},{%0,%1,%2,%3};"
        : "+f"(c[0]), "+f"(c[1]), "+f"(c[2]), "+f"(c[3])
        : "r"(a[0]), "r"(a[1]), "r"(a[2]), "r"(a[3]), "r"(b0), "r"(b1));
}

__device__ __forceinline__ unsigned s2u(const void* p) {
    return (unsigned)__cvta_generic_to_shared(p);
}
__device__ __forceinline__ void cp16(unsigned dst, const void* src, int srcsz) {
    asm volatile("cp.async.cg.shared.global [%0], [%1], 16, %2;"
                 :: "r"(dst), "l"(src), "r"(srcsz));
}
#define CP_COMMIT() asm volatile("cp.async.commit_group;")
#define CP_WAIT1()  asm volatile("cp.async.wait_group 1;")

__device__ __forceinline__ float pow36f(float q) {
    float q2 = q * q, q4 = q2 * q2, q8 = q4 * q4, q16 = q8 * q8, q32 = q16 * q16;
    return q32 * q4;
}

// ================= Stage 0: EMA coefficients + weight rounding =================
__global__ void coef_kernel(const float* __restrict__ delta, const float* __restrict__ alpha,
                            const float* __restrict__ beta,  const float* __restrict__ gamma) {
    int idx = blockIdx.x * blockDim.x + threadIdx.x;
    if (idx >= 2 * DIM_ * NDIM_) return;
    int d = idx / NDIM_;
    int n = idx % NDIM_;
    float p  = 1.f / (1.f + expf(-delta[idx]));
    float sa = 1.f / (1.f + expf(-alpha[idx]));
    g_cq[n][d] = 1.f - p * sa;
    g_cc[n][d] = p * beta[idx] * gamma[idx] * 0.25f;
}

__global__ void wcvt_kernel(const float* __restrict__ wqk, const float* __restrict__ wv,
                            const float* __restrict__ wo) {
    int i = blockIdx.x * 256 + threadIdx.x;
    if (i < 512 * 1024) g_wqk[i] = f2tff(wqk[i]);
    if (i < 512 * 512) {
        g_wv[i] = f2tff(wv[i]);
        g_wo[i] = f2tff(wo[i]);
    }
}

// ================= Stage 1: fused bidirectional EMA =================
#define ESM_STATE (ECH * NDIM_ * 17)          // 4352 floats
#define ESM_Y     (ECL * ECH * 17)            // 9792 floats
#define ESM_TOTAL (2 * ESM_STATE + ESM_Y)     // 18496 floats

__global__ void __launch_bounds__(256, 2) ema_fused(const float* __restrict__ x,
                                                    const float* __restrict__ omega) {
    extern __shared__ float es[];
    float* Sf = es;
    float* Sb = es + ESM_STATE;
    float* Ys = es + 2 * ESM_STATE;

    int tid = threadIdx.x;
    int c = tid >> 4, dl = tid & 15;
    int d = blockIdx.x * 16 + dl;
    int b = blockIdx.z;
    const float* xb = x    + (size_t)b * N_ * DIM_ + d;
    float*       yb = g_xm + (size_t)b * N_ * DIM_ + d;
    int t0 = c * ECL;

    if (tid < 16) yb[0] = f2tff(xb[0]);   // cls token passthrough (rounded)

    float q[NDIM_], q2[NDIM_], s[NDIM_];
#pragma unroll
    for (int n = 0; n < NDIM_; n++) { q[n] = g_cq[n][d]; s[n] = 0.f; }
#pragma unroll 4
    for (int tl = 0; tl < ECL; tl++) {
        float xv = xb[(size_t)(t0 + tl + 1) * DIM_];
#pragma unroll
        for (int n = 0; n < NDIM_; n++) s[n] = q[n] * s[n] + xv;
    }
#pragma unroll
    for (int n = 0; n < NDIM_; n++) Sf[(c * NDIM_ + n) * 17 + dl] = s[n];

#pragma unroll
    for (int n = 0; n < NDIM_; n++) { q2[n] = g_cq[n][d + DIM_]; s[n] = 0.f; }
#pragma unroll 4
    for (int tl = ECL - 1; tl >= 0; tl--) {
        float xv = xb[(size_t)(t0 + tl + 1) * DIM_];
#pragma unroll
        for (int n = 0; n < NDIM_; n++) s[n] = q2[n] * s[n] + xv;
    }
#pragma unroll
    for (int n = 0; n < NDIM_; n++) Sb[(c * NDIM_ + n) * 17 + dl] = s[n];
    __syncthreads();

    float cc[NDIM_];
#pragma unroll
    for (int n = 0; n < NDIM_; n++) {
        float qp = pow36f(q[n]);
        float Sin = 0.f;
        for (int cp = 0; cp < c; cp++)
            Sin = qp * Sin + Sf[(cp * NDIM_ + n) * 17 + dl];
        s[n] = Sin;
        cc[n] = g_cc[n][d];
    }
#pragma unroll 4
    for (int tl = 0; tl < ECL; tl++) {
        float xv = xb[(size_t)(t0 + tl + 1) * DIM_];
        float a[4] = {0.f, 0.f, 0.f, 0.f};
#pragma unroll
        for (int n = 0; n < NDIM_; n++) { s[n] = q[n] * s[n] + xv; a[n >> 2] += cc[n] * s[n]; }
        Ys[tl * (ECH * 17) + c * 17 + dl] = (a[0] + a[1]) + (a[2] + a[3]);
    }

#pragma unroll
    for (int n = 0; n < NDIM_; n++) {
        float qp = pow36f(q2[n]);
        float Sin = 0.f;
        for (int cp = ECH - 1; cp > c; cp--)
            Sin = qp * Sin + Sb[(cp * NDIM_ + n) * 17 + dl];
        s[n] = Sin;
        cc[n] = g_cc[n][d + DIM_];
    }
    float om = omega[d];
#pragma unroll 4
    for (int tl = ECL - 1; tl >= 0; tl--) {
        float xv = xb[(size_t)(t0 + tl + 1) * DIM_];
        float a[4] = {0.f, 0.f, 0.f, 0.f};
#pragma unroll
        for (int n = 0; n < NDIM_; n++) { s[n] = q2[n] * s[n] + xv; a[n >> 2] += cc[n] * s[n]; }
        float u = Ys[tl * (ECH * 17) + c * 17 + dl]
                + ((a[0] + a[1]) + (a[2] + a[3])) + xv * om;
        yb[(size_t)(t0 + tl + 1) * DIM_] = f2tff(u / (1.f + __expf(-u)));
    }
}

// ================= tf32 GEMM: 128x128 tile, 4 warps 64x64, 2-stage, persistent =================
#define ASLAB (128 * 36)
#define BSLAB (32 * 136)
#define GSMEM_BYTES (2 * (ASLAB + BSLAB) * 4)   // 71680 B -> 3 CTAs/SM

__device__ __forceinline__ void gemm_tile(const float* __restrict__ A, const float* __restrict__ Bm,
                                          float* __restrict__ C, int M, int Nn,
                                          const float* __restrict__ bias, int bnb, int bmb, bool rnd) {
    extern __shared__ float gsm[];
    float* As = gsm;
    float* Bs = gsm + 2 * ASLAB;
    unsigned as_u = s2u(As), bs_u = s2u(Bs);

    int tid = threadIdx.x, lane = tid & 31, w = tid >> 5;
    int gr = lane >> 2, tg = lane & 3;
    int wm = w & 1, wn = w >> 1;
    int bm = bmb * 128, bn = bnb * 128;

#define GEMM_ISSUE(s)                                                                  \
    do {                                                                               \
        int _buf = (s) & 1, _k0 = (s) * 32;                                            \
        unsigned _ad = as_u + (unsigned)(_buf * ASLAB * 4);                            \
        unsigned _bd = bs_u + (unsigned)(_buf * BSLAB * 4);                            \
        _Pragma("unroll")                                                              \
        for (int it = 0; it < 8; it++) {                                               \
            int idx = tid + it * 128;                                                  \
            int row = idx >> 3, kq = (idx & 7) * 4;                                    \
            bool ok = (bm + row < M);                                                  \
            const float* src = A + (size_t)(ok ? bm + row : 0) * 512 + _k0 + kq;       \
            cp16(_ad + (unsigned)((row * 36 + kq) * 4), src, ok ? 16 : 0);             \
        }                                                                              \
        _Pragma("unroll")                                                              \
        for (int it = 0; it < 8; it++) {                                               \
            int idx = tid + it * 128;                                                  \
            int kr = idx >> 5, nq = (idx & 31) * 4;                                    \
            cp16(_bd + (unsigned)((kr * 136 + nq) * 4),                                \
                 Bm + (size_t)(_k0 + kr) * Nn + bn + nq, 16);                          \
        }                                                                              \
    } while (0)

    GEMM_ISSUE(0); CP_COMMIT();

    float acc[4][8][4];
#pragma unroll
    for (int mt = 0; mt < 4; mt++)
#pragma unroll
        for (int nt = 0; nt < 8; nt++)
#pragma unroll
            for (int e = 0; e < 4; e++) acc[mt][nt][e] = 0.f;

    for (int s = 0; s < 16; s++) {
        __syncthreads();                       // prior compute done: other buffer free
        if (s + 1 < 16) GEMM_ISSUE(s + 1);
        CP_COMMIT();
        CP_WAIT1();                            // slab s arrived
        __syncthreads();
        const float* Ab = As + (s & 1) * ASLAB;
        const float* Bb = Bs + (s & 1) * BSLAB;
#pragma unroll
        for (int kk = 0; kk < 4; kk++) {
            unsigned a[4][4];
#pragma unroll
            for (int mt = 0; mt < 4; mt++) {
                int r = wm * 64 + mt * 16 + gr;
                int cidx = kk * 8 + tg;
                a[mt][0] = __float_as_uint(Ab[r * 36 + cidx]);
                a[mt][1] = __float_as_uint(Ab[(r + 8) * 36 + cidx]);
                a[mt][2] = __float_as_uint(Ab[r * 36 + cidx + 4]);
                a[mt][3] = __float_as_uint(Ab[(r + 8) * 36 + cidx + 4]);
            }
            unsigned bf[8][2];
#pragma unroll
            for (int nt = 0; nt < 8; nt++) {
                int col = wn * 64 + nt * 8 + gr;
                bf[nt][0] = __float_as_uint(Bb[(kk * 8 + tg) * 136 + col]);
                bf[nt][1] = __float_as_uint(Bb[(kk * 8 + tg + 4) * 136 + col]);
            }
#pragma unroll
            for (int nt = 0; nt < 8; nt++)
#pragma unroll
                for (int mt = 0; mt < 4; mt++) mma8(acc[mt][nt], a[mt], bf[nt][0], bf[nt][1]);
        }
    }
#pragma unroll
    for (int mt = 0; mt < 4; mt++) {
        int r0 = bm + wm * 64 + mt * 16 + gr;
#pragma unroll
        for (int nt = 0; nt < 8; nt++) {
            int col = bn + wn * 64 + nt * 8 + 2 * tg;
            float bx = bias ? bias[col] : 0.f, by = bias ? bias[col + 1] : 0.f;
            float e0 = acc[mt][nt][0] + bx, e1 = acc[mt][nt][1] + by;
            float e2 = acc[mt][nt][2] + bx, e3 = acc[mt][nt][3] + by;
            if (rnd) { e0 = f2tff(e0); e1 = f2tff(e1); e2 = f2tff(e2); e3 = f2tff(e3); }
            if (r0 < M)     *(float2*)(C + (size_t)r0 * Nn + col)       = make_float2(e0, e1);
            if (r0 + 8 < M) *(float2*)(C + (size_t)(r0 + 8) * Nn + col) = make_float2(e2, e3);
        }
    }
#undef GEMM_ISSUE
}

#define MB_ ((M_ROWS + 127) / 128)   // 145
#define GEMM_GRID 444                // 148 SMs x 3 CTAs

// persistent: qk tiles [0,1160) = 145x8, v tiles [1160,1740) = 145x4
__global__ void __launch_bounds__(128, 3) gemm_qkv_tc() {
    for (int t = blockIdx.x; t < MB_ * 12; t += GEMM_GRID) {
        if (t < MB_ * 8)
            gemm_tile(g_xm, g_wqk, g_qk, M_ROWS, 1024, nullptr, t & 7, t >> 3, true);
        else {
            int tt = t - MB_ * 8;
            gemm_tile(g_xm, g_wv, g_v, M_ROWS, 512, nullptr, tt & 3, tt >> 2, true);
        }
    }
}
__global__ void __launch_bounds__(128, 3) gemm_out_tc(const float* __restrict__ bias,
                                                      float* __restrict__ out) {
    for (int t = blockIdx.x; t < MB_ * 4; t += GEMM_GRID)
        gemm_tile(g_ao, g_wo, out, M_ROWS, 512, bias, t & 3, t >> 2, false);
}

// ================= Stage 3: flash attention, cp.async 2-stage K/V =================
#define KSTR 68
#define VSTR 72
#define PSTR 68
#define QROWS 96
#define KBUF (64 * KSTR)
#define VBUF (64 * VSTR)
#define NT_ ((N_ + 63) / 64)    // 10
#define FSMEM_FLOATS (2 * KBUF + 2 * VBUF + QROWS * PSTR + (2 * N_ - 1))

__global__ void __launch_bounds__(192, 2) flash_attn_tc(const float* __restrict__ rb) {
    extern __shared__ float sm[];
    float* Ks  = sm;
    float* Vs  = sm + 2 * KBUF;
    float* Ps  = sm + 2 * KBUF + 2 * VBUF;
    float* RBs = Ps + QROWS * PSTR;
    unsigned ks_u = s2u(Ks), vs_u = s2u(Vs);

    int b = blockIdx.z, h = blockIdx.y;
    int i0 = blockIdx.x * QROWS;
    int tid = threadIdx.x, lane = tid & 31, w = tid >> 5;
    int gr = lane >> 2, tg = lane & 3;

    const float* qb = g_qk + (size_t)b * N_ * 1024 + h * 64;
    const float* kb = qb + 512;
    const float* vb = g_v + (size_t)b * N_ * 512 + h * 64;

    for (int t = tid; t < 2 * N_ - 1; t += 192) RBs[t] = rb[t];

#define FL_ISSUE(jt)                                                                   \
    do {                                                                               \
        int _buf = (jt) & 1, _j0 = (jt) * 64;                                          \
        unsigned _kd = ks_u + (unsigned)(_buf * KBUF * 4);                             \
        unsigned _vd = vs_u + (unsigned)(_buf * VBUF * 4);                             \
        for (int idx = tid; idx < 1024; idx += 192) {                                  \
            int row = idx >> 4, cq = (idx & 15) * 4;                                   \
            int j = _j0 + row;                                                         \
            bool ok = (j < N_);                                                        \
            int js = ok ? j : 0;                                                       \
            cp16(_kd + (unsigned)((row * KSTR + cq) * 4),                              \
                 kb + (size_t)js * 1024 + cq, ok ? 16 : 0);                            \
            cp16(_vd + (unsigned)((row * VSTR + cq) * 4),                              \
                 vb + (size_t)js * 512 + cq, ok ? 16 : 0);                             \
        }                                                                              \
    } while (0)

    unsigned qa[8][4];
    int rlo = i0 + w * 16 + gr;
    int rhi = rlo + 8;
#pragma unroll
    for (int kk = 0; kk < 8; kk++) {
        int c0 = kk * 8 + tg;
        float v0 = (rlo < N_) ? 0.125f * qb[(size_t)rlo * 1024 + c0]     : 0.f;
        float v1 = (rhi < N_) ? 0.125f * qb[(size_t)rhi * 1024 + c0]     : 0.f;
        float v2 = (rlo < N_) ? 0.125f * qb[(size_t)rlo * 1024 + c0 + 4] : 0.f;
        float v3 = (rhi < N_) ? 0.125f * qb[(size_t)rhi * 1024 + c0 + 4] : 0.f;
        qa[kk][0] = __float_as_uint(v0); qa[kk][1] = __float_as_uint(v1);
        qa[kk][2] = __float_as_uint(v2); qa[kk][3] = __float_as_uint(v3);
    }

    FL_ISSUE(0); CP_COMMIT();

    float o[8][4], ob[8][4];
#pragma unroll
    for (int nt = 0; nt < 8; nt++)
#pragma unroll
        for (int e = 0; e < 4; e++) { o[nt][e] = 0.f; ob[nt][e] = 0.f; }
    float mlo = -1e30f, mhi = -1e30f, zlo = 0.f, zhi = 0.f;

    for (int jt = 0; jt < NT_; jt++) {
        int j0 = jt * 64;
        bool full = (j0 + 64 <= N_);
        __syncthreads();
        if (jt + 1 < NT_) FL_ISSUE(jt + 1);
        CP_COMMIT();
        CP_WAIT1();
        __syncthreads();
        const float* Ksb = Ks + (jt & 1) * KBUF;
        const float* Vsb = Vs + (jt & 1) * VBUF;

        float s[8][4];
#pragma unroll
        for (int nt = 0; nt < 8; nt++) {
#pragma unroll
            for (int e = 0; e < 4; e++) s[nt][e] = 0.f;
#pragma unroll
            for (int kk = 0; kk < 8; kk++) {
                unsigned b0 = __float_as_uint(Ksb[(nt * 8 + gr) * KSTR + kk * 8 + tg]);
                unsigned b1 = __float_as_uint(Ksb[(nt * 8 + gr) * KSTR + kk * 8 + tg + 4]);
                mma8(s[nt], qa[kk], b0, b1);
            }
        }

        float tlo = -1e30f, thi = -1e30f;
#pragma unroll
        for (int nt = 0; nt < 8; nt++) {
            int col = j0 + nt * 8 + 2 * tg;
            if (full || col < N_)     { tlo = fmaxf(tlo, s[nt][0]); thi = fmaxf(thi, s[nt][2]); }
            if (full || col + 1 < N_) { tlo = fmaxf(tlo, s[nt][1]); thi = fmaxf(thi, s[nt][3]); }
        }
#pragma unroll
        for (int off = 1; off <= 2; off <<= 1) {
            tlo = fmaxf(tlo, __shfl_xor_sync(0xffffffffu, tlo, off));
            thi = fmaxf(thi, __shfl_xor_sync(0xffffffffu, thi, off));
        }
        float mlon = fmaxf(mlo, tlo), mhin = fmaxf(mhi, thi);
        float sclo = __expf(mlo - mlon), schi = __expf(mhi - mhin);
        float psl = 0.f, psh = 0.f;
        int prow_lo = (w * 16 + gr) * PSTR;
        int prow_hi = (w * 16 + gr + 8) * PSTR;
#pragma unroll
        for (int nt = 0; nt < 8; nt++) {
            int col = j0 + nt * 8 + 2 * tg;
            float p0 = (full || col     < N_) ? __expf(s[nt][0] - mlon) : 0.f;
            float p1 = (full || col + 1 < N_) ? __expf(s[nt][1] - mlon) : 0.f;
            float p2 = (full || col     < N_) ? __expf(s[nt][2] - mhin) : 0.f;
            float p3 = (full || col + 1 < N_) ? __expf(s[nt][3] - mhin) : 0.f;
            psl += p0 + p1; psh += p2 + p3;
            o[nt][0] *= sclo; o[nt][1] *= sclo;
            o[nt][2] *= schi; o[nt][3] *= schi;
            *(float2*)(Ps + prow_lo + nt * 8 + 2 * tg) = make_float2(f2tff(p0), f2tff(p1));
            *(float2*)(Ps + prow_hi + nt * 8 + 2 * tg) = make_float2(f2tff(p2), f2tff(p3));
        }
#pragma unroll
        for (int off = 1; off <= 2; off <<= 1) {
            psl += __shfl_xor_sync(0xffffffffu, psl, off);
            psh += __shfl_xor_sync(0xffffffffu, psh, off);
        }
        zlo = zlo * sclo + psl;  zhi = zhi * schi + psh;
        mlo = mlon;  mhi = mhin;
        __syncwarp();

#pragma unroll
        for (int kk = 0; kk < 8; kk++) {
            unsigned pa[4], ba[4];
            int pc = kk * 8 + tg;
            pa[0] = __float_as_uint(Ps[prow_lo + pc]);
            pa[1] = __float_as_uint(Ps[prow_hi + pc]);
            pa[2] = __float_as_uint(Ps[prow_lo + pc + 4]);
            pa[3] = __float_as_uint(Ps[prow_hi + pc + 4]);
            int jlo = j0 + kk * 8 + tg, jhi = jlo + 4;
            float b00 = (rlo < N_ && jlo < N_) ? RBs[576 + jlo - rlo] : 0.f;
            float b01 = (rhi < N_ && jlo < N_) ? RBs[576 + jlo - rhi] : 0.f;
            float b02 = (rlo < N_ && jhi < N_) ? RBs[576 + jhi - rlo] : 0.f;
            float b03 = (rhi < N_ && jhi < N_) ? RBs[576 + jhi - rhi] : 0.f;
            ba[0] = f2tf(b00); ba[1] = f2tf(b01); ba[2] = f2tf(b02); ba[3] = f2tf(b03);
#pragma unroll
            for (int nt = 0; nt < 8; nt++) {
                unsigned v0 = __float_as_uint(Vsb[(kk * 8 + tg) * VSTR + nt * 8 + gr]);
                unsigned v1 = __float_as_uint(Vsb[(kk * 8 + tg + 4) * VSTR + nt * 8 + gr]);
                mma8(o[nt],  pa, v0, v1);
                mma8(ob[nt], ba, v0, v1);
            }
        }
        __syncwarp();
    }

    float izlo = 1.f / zlo, izhi = 1.f / zhi;
#pragma unroll
    for (int nt = 0; nt < 8; nt++) {
        int col = h * 64 + nt * 8 + 2 * tg;
        if (rlo < N_) {
            float2 v = make_float2(f2tff(o[nt][0] * izlo + ob[nt][0]),
                                   f2tff(o[nt][1] * izlo + ob[nt][1]));
            *(float2*)(g_ao + ((size_t)b * N_ + rlo) * 512 + col) = v;
        }
        if (rhi < N_) {
            float2 v = make_float2(f2tff(o[nt][2] * izhi + ob[nt][2]),
                                   f2tff(o[nt][3] * izhi + ob[nt][3]));
            *(float2*)(g_ao + ((size_t)b * N_ + rhi) * 512 + col) = v;
        }
    }
#undef FL_ISSUE
}

// ================= launch =================
extern "C" void kernel_launch(void* const* d_in, const int* in_sizes, int n_in,
                              void* d_out, int out_size) {
    const float* x         = (const float*)d_in[0];
    const float* W_qk      = (const float*)d_in[1];
    const float* W_v       = (const float*)d_in[2];
    const float* W_out     = (const float*)d_in[3];
    const float* b_out     = (const float*)d_in[4];
    const float* rel_bias  = (const float*)d_in[5];
    const float* ema_delta = (const float*)d_in[6];
    const float* ema_alpha = (const float*)d_in[7];
    const float* ema_beta  = (const float*)d_in[8];
    const float* ema_gamma = (const float*)d_in[9];
    const float* ema_omega = (const float*)d_in[10];
    float* out = (float*)d_out;

    static int attr_set = 0;
    if (!attr_set) {
        cudaFuncSetAttribute(ema_fused, cudaFuncAttributeMaxDynamicSharedMemorySize,
                             ESM_TOTAL * (int)sizeof(float));
        cudaFuncSetAttribute(gemm_qkv_tc, cudaFuncAttributeMaxDynamicSharedMemorySize, GSMEM_BYTES);
        cudaFuncSetAttribute(gemm_out_tc, cudaFuncAttributeMaxDynamicSharedMemorySize, GSMEM_BYTES);
        cudaFuncSetAttribute(flash_attn_tc, cudaFuncAttributeMaxDynamicSharedMemorySize,
                             FSMEM_FLOATS * (int)sizeof(float));
        attr_set = 1;
    }

    coef_kernel<<<(2 * DIM_ * NDIM_ + 255) / 256, 256>>>(ema_delta, ema_alpha, ema_beta, ema_gamma);
    wcvt_kernel<<<(512 * 1024 + 255) / 256, 256>>>(W_qk, W_v, W_out);
    ema_fused<<<dim3(DIM_ / 16, 1, B_), 256, ESM_TOTAL * sizeof(float)>>>(x, ema_omega);

    gemm_qkv_tc<<<GEMM_GRID, 128, GSMEM_BYTES>>>();

    flash_attn_tc<<<dim3((N_ + QROWS - 1) / QROWS, HEADS_, B_), 192,
                    FSMEM_FLOATS * sizeof(float)>>>(rel_bias);

    gemm_out_tc<<<GEMM_GRID, 128, GSMEM_BYTES>>>(b_out, out);
}

// round 11
// speedup vs baseline: 1.0923x; 1.0382x over previous
#include <cuda_runtime.h>
#include <cuda_fp16.h>

#define B_     32
#define N_     577
#define L_     576
#define DIM_   512
#define HEADS_ 8
#define NDIM_  16
#define M_ROWS (B_ * N_)   // 18464
#define ECH 16
#define ECL 36

// -------- scratch (device globals) --------
__device__ float g_xm[(size_t)B_ * N_ * DIM_];
__device__ float g_qk[(size_t)B_ * N_ * 1024];
__device__ float g_v [(size_t)B_ * N_ * 512];
__device__ __align__(16) __half g_ao16[(size_t)B_ * N_ * 512];  // attn out (fp16)
__device__ float g_cq[NDIM_][2 * DIM_];
__device__ float g_cc[NDIM_][2 * DIM_];
__device__ float g_wqk[512 * 1024];
__device__ float g_wv [512 * 512];
__device__ __align__(16) __half g_wo16[512 * 512];              // W_out^T [n][k] fp16

// ---------------- helpers ----------------
__device__ __forceinline__ unsigned f2tf(float x) {
    unsigned u;
    asm("cvt.rna.tf32.f32 %0, %1;" : "=r"(u) : "f"(x));
    return u;
}
__device__ __forceinline__ float f2tff(float x) { return __uint_as_float(f2tf(x)); }
__device__ __forceinline__ unsigned pack2(float x, float y) {
    __half2 h = __floats2half2_rn(x, y);
    return *reinterpret_cast<unsigned*>(&h);
}
__device__ __forceinline__ void mma8(float* c, const unsigned* a, unsigned b0, unsigned b1) {
    asm volatile(
        "mma.sync.aligned.m16n8k8.row.col.f32.tf32.tf32.f32 "
        "{%0,%1,%2,%3},{%4,%5,%6,%7},{%8,%9},{%0,%1,%2,%3};"
        : "+f"(c[0]), "+f"(c[1]), "+f"(c[2]), "+f"(c[3])
        : "r"(a[0]), "r"(a[1]), "r"(a[2]), "r"(a[3]), "r"(b0), "r"(b1));
}
__device__ __forceinline__ void mma16(float* c, const unsigned* a, unsigned b0, unsigned b1) {
    asm volatile(
        "mma.sync.aligned.m16n8k16.row.col.f32.f16.f16.f32 "
        "{%0,%1,%2,%3},{%4,%5,%6,%7},{%8,%9},{%0,%1,%2,%3};"
        : "+f"(c[0]), "+f"(c[1]), "+f"(c[2]), "+f"(c[3])
        : "r"(a[0]), "r"(a[1]), "r"(a[2]), "r"(a[3]), "r"(b0), "r"(b1));
}
__device__ __forceinline__ unsigned s2u(const void* p) {
    return (unsigned)__cvta_generic_to_shared(p);
}
__device__ __forceinline__ void cp16(unsigned dst, const void* src, int srcsz) {
    asm volatile("cp.async.cg.shared.global [%0], [%1], 16, %2;"
                 :: "r"(dst), "l"(src), "r"(srcsz));
}
#define CP_COMMIT() asm volatile("cp.async.commit_group;")
#define CP_WAIT1()  asm volatile("cp.async.wait_group 1;")

__device__ __forceinline__ float pow36f(float q) {
    float q2 = q * q, q4 = q2 * q2, q8 = q4 * q4, q16 = q8 * q8, q32 = q16 * q16;
    return q32 * q4;
}

// ================= Stage 0: EMA coefficients + weight prep =================
__global__ void coef_kernel(const float* __restrict__ delta, const float* __restrict__ alpha,
                            const float* __restrict__ beta,  const float* __restrict__ gamma) {
    int idx = blockIdx.x * blockDim.x + threadIdx.x;
    if (idx >= 2 * DIM_ * NDIM_) return;
    int d = idx / NDIM_;
    int n = idx % NDIM_;
    float p  = 1.f / (1.f + expf(-delta[idx]));
    float sa = 1.f / (1.f + expf(-alpha[idx]));
    g_cq[n][d] = 1.f - p * sa;
    g_cc[n][d] = p * beta[idx] * gamma[idx] * 0.25f;
}

__global__ void wcvt_kernel(const float* __restrict__ wqk, const float* __restrict__ wv) {
    int i = blockIdx.x * 256 + threadIdx.x;
    if (i < 512 * 1024) g_wqk[i] = f2tff(wqk[i]);
    if (i < 512 * 512)  g_wv[i]  = f2tff(wv[i]);
}

// W_out [512][512] f32 row-major (k,n) -> g_wo16 [n][k] f16 (trivial, no smem)
__global__ void tcvt_simple(const float* __restrict__ src) {
    int i = blockIdx.x * 256 + threadIdx.x;
    if (i >= 512 * 512) return;
    int n = i >> 9, k = i & 511;
    g_wo16[i] = __float2half_rn(src[(size_t)k * 512 + n]);
}

// ================= Stage 1: fused bidirectional EMA (round-8 verbatim) =========
#define ESM_STATE (ECH * NDIM_ * 17)
#define ESM_Y     (ECL * ECH * 17)
#define ESM_TOTAL (2 * ESM_STATE + ESM_Y)

__global__ void __launch_bounds__(256, 2) ema_fused(const float* __restrict__ x,
                                                    const float* __restrict__ omega) {
    extern __shared__ float es[];
    float* Sf = es;
    float* Sb = es + ESM_STATE;
    float* Ys = es + 2 * ESM_STATE;

    int tid = threadIdx.x;
    int c = tid >> 4, dl = tid & 15;
    int d = blockIdx.x * 16 + dl;
    int b = blockIdx.z;
    const float* xb = x    + (size_t)b * N_ * DIM_ + d;
    float*       yb = g_xm + (size_t)b * N_ * DIM_ + d;
    int t0 = c * ECL;

    if (tid < 16) yb[0] = f2tff(xb[0]);   // cls token passthrough

    float q[NDIM_], q2[NDIM_], s[NDIM_];
#pragma unroll
    for (int n = 0; n < NDIM_; n++) { q[n] = g_cq[n][d]; s[n] = 0.f; }
#pragma unroll 4
    for (int tl = 0; tl < ECL; tl++) {
        float xv = xb[(size_t)(t0 + tl + 1) * DIM_];
#pragma unroll
        for (int n = 0; n < NDIM_; n++) s[n] = q[n] * s[n] + xv;
    }
#pragma unroll
    for (int n = 0; n < NDIM_; n++) Sf[(c * NDIM_ + n) * 17 + dl] = s[n];

#pragma unroll
    for (int n = 0; n < NDIM_; n++) { q2[n] = g_cq[n][d + DIM_]; s[n] = 0.f; }
#pragma unroll 4
    for (int tl = ECL - 1; tl >= 0; tl--) {
        float xv = xb[(size_t)(t0 + tl + 1) * DIM_];
#pragma unroll
        for (int n = 0; n < NDIM_; n++) s[n] = q2[n] * s[n] + xv;
    }
#pragma unroll
    for (int n = 0; n < NDIM_; n++) Sb[(c * NDIM_ + n) * 17 + dl] = s[n];
    __syncthreads();

    float cc[NDIM_];
#pragma unroll
    for (int n = 0; n < NDIM_; n++) {
        float qp = pow36f(q[n]);
        float Sin = 0.f;
        for (int cp = 0; cp < c; cp++)
            Sin = qp * Sin + Sf[(cp * NDIM_ + n) * 17 + dl];
        s[n] = Sin;
        cc[n] = g_cc[n][d];
    }
#pragma unroll 4
    for (int tl = 0; tl < ECL; tl++) {
        float xv = xb[(size_t)(t0 + tl + 1) * DIM_];
        float a[4] = {0.f, 0.f, 0.f, 0.f};
#pragma unroll
        for (int n = 0; n < NDIM_; n++) { s[n] = q[n] * s[n] + xv; a[n >> 2] += cc[n] * s[n]; }
        Ys[tl * (ECH * 17) + c * 17 + dl] = (a[0] + a[1]) + (a[2] + a[3]);
    }

#pragma unroll
    for (int n = 0; n < NDIM_; n++) {
        float qp = pow36f(q2[n]);
        float Sin = 0.f;
        for (int cp = ECH - 1; cp > c; cp--)
            Sin = qp * Sin + Sb[(cp * NDIM_ + n) * 17 + dl];
        s[n] = Sin;
        cc[n] = g_cc[n][d + DIM_];
    }
    float om = omega[d];
#pragma unroll 4
    for (int tl = ECL - 1; tl >= 0; tl--) {
        float xv = xb[(size_t)(t0 + tl + 1) * DIM_];
        float a[4] = {0.f, 0.f, 0.f, 0.f};
#pragma unroll
        for (int n = 0; n < NDIM_; n++) { s[n] = q2[n] * s[n] + xv; a[n >> 2] += cc[n] * s[n]; }
        float u = Ys[tl * (ECH * 17) + c * 17 + dl]
                + ((a[0] + a[1]) + (a[2] + a[3])) + xv * om;
        yb[(size_t)(t0 + tl + 1) * DIM_] = f2tff(u / (1.f + __expf(-u)));
    }
}

// ======= tf32 GEMM (round-8 verbatim): 128x128, 4 warps 64x64, 2-stage =========
#define ASLAB (128 * 36)
#define BSLAB (32 * 136)
#define GSMEM_BYTES (2 * (ASLAB + BSLAB) * 4)   // 71680 B

__device__ __forceinline__ void gemm_tile(const float* __restrict__ A, const float* __restrict__ Bm,
                                          float* __restrict__ C, int M, int Nn,
                                          int bnb, int bmb) {
    extern __shared__ float gsm[];
    float* As = gsm;
    float* Bs = gsm + 2 * ASLAB;
    unsigned as_u = s2u(As), bs_u = s2u(Bs);

    int tid = threadIdx.x, lane = tid & 31, w = tid >> 5;
    int gr = lane >> 2, tg = lane & 3;
    int wm = w & 1, wn = w >> 1;
    int bm = bmb * 128, bn = bnb * 128;

#define GEMM_ISSUE(s)                                                                  \
    do {                                                                               \
        int _buf = (s) & 1, _k0 = (s) * 32;                                            \
        unsigned _ad = as_u + (unsigned)(_buf * ASLAB * 4);                            \
        unsigned _bd = bs_u + (unsigned)(_buf * BSLAB * 4);                            \
        _Pragma("unroll")                                                              \
        for (int it = 0; it < 8; it++) {                                               \
            int idx = tid + it * 128;                                                  \
            int row = idx >> 3, kq = (idx & 7) * 4;                                    \
            bool ok = (bm + row < M);                                                  \
            const float* src = A + (size_t)(ok ? bm + row : 0) * 512 + _k0 + kq;       \
            cp16(_ad + (unsigned)((row * 36 + kq) * 4), src, ok ? 16 : 0);             \
        }                                                                              \
        _Pragma("unroll")                                                              \
        for (int it = 0; it < 8; it++) {                                               \
            int idx = tid + it * 128;                                                  \
            int kr = idx >> 5, nq = (idx & 31) * 4;                                    \
            cp16(_bd + (unsigned)((kr * 136 + nq) * 4),                                \
                 Bm + (size_t)(_k0 + kr) * Nn + bn + nq, 16);                          \
        }                                                                              \
    } while (0)

    GEMM_ISSUE(0); CP_COMMIT();

    float acc[4][8][4];
#pragma unroll
    for (int mt = 0; mt < 4; mt++)
#pragma unroll
        for (int nt = 0; nt < 8; nt++)
#pragma unroll
            for (int e = 0; e < 4; e++) acc[mt][nt][e] = 0.f;

    for (int s = 0; s < 16; s++) {
        __syncthreads();
        if (s + 1 < 16) GEMM_ISSUE(s + 1);
        CP_COMMIT();
        CP_WAIT1();
        __syncthreads();
        const float* Ab = As + (s & 1) * ASLAB;
        const float* Bb = Bs + (s & 1) * BSLAB;
#pragma unroll
        for (int kk = 0; kk < 4; kk++) {
            unsigned a[4][4];
#pragma unroll
            for (int mt = 0; mt < 4; mt++) {
                int r = wm * 64 + mt * 16 + gr;
                int cidx = kk * 8 + tg;
                a[mt][0] = __float_as_uint(Ab[r * 36 + cidx]);
                a[mt][1] = __float_as_uint(Ab[(r + 8) * 36 + cidx]);
                a[mt][2] = __float_as_uint(Ab[r * 36 + cidx + 4]);
                a[mt][3] = __float_as_uint(Ab[(r + 8) * 36 + cidx + 4]);
            }
            unsigned bf[8][2];
#pragma unroll
            for (int nt = 0; nt < 8; nt++) {
                int col = wn * 64 + nt * 8 + gr;
                bf[nt][0] = __float_as_uint(Bb[(kk * 8 + tg) * 136 + col]);
                bf[nt][1] = __float_as_uint(Bb[(kk * 8 + tg + 4) * 136 + col]);
            }
#pragma unroll
            for (int nt = 0; nt < 8; nt++)
#pragma unroll
                for (int mt = 0; mt < 4; mt++) mma8(acc[mt][nt], a[mt], bf[nt][0], bf[nt][1]);
        }
    }
#pragma unroll
    for (int mt = 0; mt < 4; mt++) {
        int r0 = bm + wm * 64 + mt * 16 + gr;
#pragma unroll
        for (int nt = 0; nt < 8; nt++) {
            int col = bn + wn * 64 + nt * 8 + 2 * tg;
            float e0 = f2tff(acc[mt][nt][0]), e1 = f2tff(acc[mt][nt][1]);
            float e2 = f2tff(acc[mt][nt][2]), e3 = f2tff(acc[mt][nt][3]);
            if (r0 < M)     *(float2*)(C + (size_t)r0 * Nn + col)       = make_float2(e0, e1);
            if (r0 + 8 < M) *(float2*)(C + (size_t)(r0 + 8) * Nn + col) = make_float2(e2, e3);
        }
    }
#undef GEMM_ISSUE
}

#define MB_ ((M_ROWS + 127) / 128)   // 145
#define GEMM_GRID 444

__global__ void __launch_bounds__(128, 3) gemm_qkv_tc() {
    for (int t = blockIdx.x; t < MB_ * 12; t += GEMM_GRID) {
        if (t < MB_ * 8)
            gemm_tile(g_xm, g_wqk, g_qk, M_ROWS, 1024, t & 7, t >> 3);
        else {
            int tt = t - MB_ * 8;
            gemm_tile(g_xm, g_wv, g_v, M_ROWS, 512, tt & 3, tt >> 2);
        }
    }
}

// ======= fp16 GEMM (NEW, out-projection only): 128x128, 2-stage cp.async ========
#define AWSTR 20
#define TSLAB (128 * AWSTR)
#define GSMEM16_BYTES (4 * TSLAB * 4)   // 40960 B

__device__ __forceinline__ void gemm16_tile(const __half* __restrict__ A,
                                            const __half* __restrict__ Bw, int M,
                                            float* __restrict__ C, int Cs,
                                            const float* __restrict__ bias,
                                            int bnb, int bmb) {
    extern __shared__ unsigned gsw[];
    unsigned* Asm = gsw;
    unsigned* Bsm = gsw + 2 * TSLAB;
    unsigned as_u = s2u(Asm), bs_u = s2u(Bsm);

    int tid = threadIdx.x, lane = tid & 31, w = tid >> 5;
    int gr = lane >> 2, tg = lane & 3;
    int wm = w & 1, wn = w >> 1;
    int bm = bmb * 128, bn = bnb * 128;

#define G16_ISSUE(s)                                                                   \
    do {                                                                               \
        int _buf = (s) & 1, _k0 = (s) * 32;                                            \
        unsigned _ad = as_u + (unsigned)(_buf * TSLAB * 4);                            \
        unsigned _bd = bs_u + (unsigned)(_buf * TSLAB * 4);                            \
        _Pragma("unroll")                                                              \
        for (int it = 0; it < 4; it++) {                                               \
            int idx = tid + it * 128;                                                  \
            int row = idx >> 2, cq = idx & 3;                                          \
            bool ok = (bm + row < M);                                                  \
            const __half* src = A + (size_t)(ok ? bm + row : 0) * 512 + _k0 + cq * 8;  \
            cp16(_ad + (unsigned)((row * AWSTR + cq * 4) * 4), src, ok ? 16 : 0);      \
        }                                                                              \
        _Pragma("unroll")                                                              \
        for (int it = 0; it < 4; it++) {                                               \
            int idx = tid + it * 128;                                                  \
            int row = idx >> 2, cq = idx & 3;                                          \
            cp16(_bd + (unsigned)((row * AWSTR + cq * 4) * 4),                         \
                 Bw + (size_t)(bn + row) * 512 + _k0 + cq * 8, 16);                    \
        }                                                                              \
    } while (0)

    G16_ISSUE(0); CP_COMMIT();

    float acc[4][8][4];
#pragma unroll
    for (int mt = 0; mt < 4; mt++)
#pragma unroll
        for (int nt = 0; nt < 8; nt++)
#pragma unroll
            for (int e = 0; e < 4; e++) acc[mt][nt][e] = 0.f;

    for (int s = 0; s < 16; s++) {
        __syncthreads();
        if (s + 1 < 16) G16_ISSUE(s + 1);
        CP_COMMIT();
        CP_WAIT1();
        __syncthreads();
        const unsigned* Ab = Asm + (s & 1) * TSLAB;
        const unsigned* Bb = Bsm + (s & 1) * TSLAB;
#pragma unroll
        for (int kk = 0; kk < 2; kk++) {
            unsigned a[4][4];
#pragma unroll
            for (int mt = 0; mt < 4; mt++) {
                int r = wm * 64 + mt * 16 + gr;
                int cw = kk * 8 + tg;
                a[mt][0] = Ab[r * AWSTR + cw];
                a[mt][1] = Ab[(r + 8) * AWSTR + cw];
                a[mt][2] = Ab[r * AWSTR + cw + 4];
                a[mt][3] = Ab[(r + 8) * AWSTR + cw + 4];
            }
            unsigned bf[8][2];
#pragma unroll
            for (int nt = 0; nt < 8; nt++) {
                int n = wn * 64 + nt * 8 + gr;
                bf[nt][0] = Bb[n * AWSTR + kk * 8 + tg];
                bf[nt][1] = Bb[n * AWSTR + kk * 8 + tg + 4];
            }
#pragma unroll
            for (int nt = 0; nt < 8; nt++)
#pragma unroll
                for (int mt = 0; mt < 4; mt++) mma16(acc[mt][nt], a[mt], bf[nt][0], bf[nt][1]);
        }
    }
#pragma unroll
    for (int mt = 0; mt < 4; mt++) {
        int r0 = bm + wm * 64 + mt * 16 + gr;
#pragma unroll
        for (int nt = 0; nt < 8; nt++) {
            int col = bn + wn * 64 + nt * 8 + 2 * tg;
            float bx = bias[col], by = bias[col + 1];
            if (r0 < M)
                *(float2*)(C + (size_t)r0 * Cs + col) =
                    make_float2(acc[mt][nt][0] + bx, acc[mt][nt][1] + by);
            if (r0 + 8 < M)
                *(float2*)(C + (size_t)(r0 + 8) * Cs + col) =
                    make_float2(acc[mt][nt][2] + bx, acc[mt][nt][3] + by);
        }
    }
#undef G16_ISSUE
}

__global__ void __launch_bounds__(128, 3) gemm_out_tc(const float* __restrict__ bias,
                                                      float* __restrict__ out) {
    for (int t = blockIdx.x; t < MB_ * 4; t += GEMM_GRID)
        gemm16_tile(g_ao16, g_wo16, M_ROWS, out, 512, bias, t & 3, t >> 2);
}

// ================= Stage 3: flash attention (round-8 verbatim, fp16 epilogue) ====
#define KSTR 68
#define VSTR 72
#define PSTR 68
#define QROWS 96
#define KBUF (64 * KSTR)
#define VBUF (64 * VSTR)
#define NT_ ((N_ + 63) / 64)
#define FSMEM_FLOATS (2 * KBUF + 2 * VBUF + QROWS * PSTR + (2 * N_ - 1))

__global__ void __launch_bounds__(192, 2) flash_attn_tc(const float* __restrict__ rb) {
    extern __shared__ float sm[];
    float* Ks  = sm;
    float* Vs  = sm + 2 * KBUF;
    float* Ps  = sm + 2 * KBUF + 2 * VBUF;
    float* RBs = Ps + QROWS * PSTR;
    unsigned ks_u = s2u(Ks), vs_u = s2u(Vs);

    int b = blockIdx.z, h = blockIdx.y;
    int i0 = blockIdx.x * QROWS;
    int tid = threadIdx.x, lane = tid & 31, w = tid >> 5;
    int gr = lane >> 2, tg = lane & 3;

    const float* qb = g_qk + (size_t)b * N_ * 1024 + h * 64;
    const float* kb = qb + 512;
    const float* vb = g_v + (size_t)b * N_ * 512 + h * 64;

    for (int t = tid; t < 2 * N_ - 1; t += 192) RBs[t] = rb[t];

#define FL_ISSUE(jt)                                                                   \
    do {                                                                               \
        int _buf = (jt) & 1, _j0 = (jt) * 64;                                          \
        unsigned _kd = ks_u + (unsigned)(_buf * KBUF * 4);                             \
        unsigned _vd = vs_u + (unsigned)(_buf * VBUF * 4);                             \
        for (int idx = tid; idx < 1024; idx += 192) {                                  \
            int row = idx >> 4, cq = (idx & 15) * 4;                                   \
            int j = _j0 + row;                                                         \
            bool ok = (j < N_);                                                        \
            int js = ok ? j : 0;                                                       \
            cp16(_kd + (unsigned)((row * KSTR + cq) * 4),                              \
                 kb + (size_t)js * 1024 + cq, ok ? 16 : 0);                            \
            cp16(_vd + (unsigned)((row * VSTR + cq) * 4),                              \
                 vb + (size_t)js * 512 + cq, ok ? 16 : 0);                             \
        }                                                                              \
    } while (0)

    unsigned qa[8][4];
    int rlo = i0 + w * 16 + gr;
    int rhi = rlo + 8;
#pragma unroll
    for (int kk = 0; kk < 8; kk++) {
        int c0 = kk * 8 + tg;
        float v0 = (rlo < N_) ? 0.125f * qb[(size_t)rlo * 1024 + c0]     : 0.f;
        float v1 = (rhi < N_) ? 0.125f * qb[(size_t)rhi * 1024 + c0]     : 0.f;
        float v2 = (rlo < N_) ? 0.125f * qb[(size_t)rlo * 1024 + c0 + 4] : 0.f;
        float v3 = (rhi < N_) ? 0.125f * qb[(size_t)rhi * 1024 + c0 + 4] : 0.f;
        qa[kk][0] = __float_as_uint(v0); qa[kk][1] = __float_as_uint(v1);
        qa[kk][2] = __float_as_uint(v2); qa[kk][3] = __float_as_uint(v3);
    }

    FL_ISSUE(0); CP_COMMIT();

    float o[8][4], ob[8][4];
#pragma unroll
    for (int nt = 0; nt < 8; nt++)
#pragma unroll
        for (int e = 0; e < 4; e++) { o[nt][e] = 0.f; ob[nt][e] = 0.f; }
    float mlo = -1e30f, mhi = -1e30f, zlo = 0.f, zhi = 0.f;

    for (int jt = 0; jt < NT_; jt++) {
        int j0 = jt * 64;
        bool full = (j0 + 64 <= N_);
        __syncthreads();
        if (jt + 1 < NT_) FL_ISSUE(jt + 1);
        CP_COMMIT();
        CP_WAIT1();
        __syncthreads();
        const float* Ksb = Ks + (jt & 1) * KBUF;
        const float* Vsb = Vs + (jt & 1) * VBUF;

        float s[8][4];
#pragma unroll
        for (int nt = 0; nt < 8; nt++) {
#pragma unroll
            for (int e = 0; e < 4; e++) s[nt][e] = 0.f;
#pragma unroll
            for (int kk = 0; kk < 8; kk++) {
                unsigned b0 = __float_as_uint(Ksb[(nt * 8 + gr) * KSTR + kk * 8 + tg]);
                unsigned b1 = __float_as_uint(Ksb[(nt * 8 + gr) * KSTR + kk * 8 + tg + 4]);
                mma8(s[nt], qa[kk], b0, b1);
            }
        }

        float tlo = -1e30f, thi = -1e30f;
#pragma unroll
        for (int nt = 0; nt < 8; nt++) {
            int col = j0 + nt * 8 + 2 * tg;
            if (full || col < N_)     { tlo = fmaxf(tlo, s[nt][0]); thi = fmaxf(thi, s[nt][2]); }
            if (full || col + 1 < N_) { tlo = fmaxf(tlo, s[nt][1]); thi = fmaxf(thi, s[nt][3]); }
        }
#pragma unroll
        for (int off = 1; off <= 2; off <<= 1) {
            tlo = fmaxf(tlo, __shfl_xor_sync(0xffffffffu, tlo, off));
            thi = fmaxf(thi, __shfl_xor_sync(0xffffffffu, thi, off));
        }
        float mlon = fmaxf(mlo, tlo), mhin = fmaxf(mhi, thi);
        float sclo = __expf(mlo - mlon), schi = __expf(mhi - mhin);
        float psl = 0.f, psh = 0.f;
        int prow_lo = (w * 16 + gr) * PSTR;
        int prow_hi = (w * 16 + gr + 8) * PSTR;
#pragma unroll
        for (int nt = 0; nt < 8; nt++) {
            int col = j0 + nt * 8 + 2 * tg;
            float p0 = (full || col     < N_) ? __expf(s[nt][0] - mlon) : 0.f;
            float p1 = (full || col + 1 < N_) ? __expf(s[nt][1] - mlon) : 0.f;
            float p2 = (full || col     < N_) ? __expf(s[nt][2] - mhin) : 0.f;
            float p3 = (full || col + 1 < N_) ? __expf(s[nt][3] - mhin) : 0.f;
            psl += p0 + p1; psh += p2 + p3;
            o[nt][0] *= sclo; o[nt][1] *= sclo;
            o[nt][2] *= schi; o[nt][3] *= schi;
            *(float2*)(Ps + prow_lo + nt * 8 + 2 * tg) = make_float2(f2tff(p0), f2tff(p1));
            *(float2*)(Ps + prow_hi + nt * 8 + 2 * tg) = make_float2(f2tff(p2), f2tff(p3));
        }
#pragma unroll
        for (int off = 1; off <= 2; off <<= 1) {
            psl += __shfl_xor_sync(0xffffffffu, psl, off);
            psh += __shfl_xor_sync(0xffffffffu, psh, off);
        }
        zlo = zlo * sclo + psl;  zhi = zhi * schi + psh;
        mlo = mlon;  mhi = mhin;
        __syncwarp();

#pragma unroll
        for (int kk = 0; kk < 8; kk++) {
            unsigned pa[4], ba[4];
            int pc = kk * 8 + tg;
            pa[0] = __float_as_uint(Ps[prow_lo + pc]);
            pa[1] = __float_as_uint(Ps[prow_hi + pc]);
            pa[2] = __float_as_uint(Ps[prow_lo + pc + 4]);
            pa[3] = __float_as_uint(Ps[prow_hi + pc + 4]);
            int jlo = j0 + kk * 8 + tg, jhi = jlo + 4;
            float b00 = (rlo < N_ && jlo < N_) ? RBs[576 + jlo - rlo] : 0.f;
            float b01 = (rhi < N_ && jlo < N_) ? RBs[576 + jlo - rhi] : 0.f;
            float b02 = (rlo < N_ && jhi < N_) ? RBs[576 + jhi - rlo] : 0.f;
            float b03 = (rhi < N_ && jhi < N_) ? RBs[576 + jhi - rhi] : 0.f;
            ba[0] = f2tf(b00); ba[1] = f2tf(b01); ba[2] = f2tf(b02); ba[3] = f2tf(b03);
#pragma unroll
            for (int nt = 0; nt < 8; nt++) {
                unsigned v0 = __float_as_uint(Vsb[(kk * 8 + tg) * VSTR + nt * 8 + gr]);
                unsigned v1 = __float_as_uint(Vsb[(kk * 8 + tg + 4) * VSTR + nt * 8 + gr]);
                mma8(o[nt],  pa, v0, v1);
                mma8(ob[nt], ba, v0, v1);
            }
        }
        __syncwarp();
    }

    // ---- epilogue: (O/Z + Ob) -> fp16 g_ao16 ----
    float izlo = 1.f / zlo, izhi = 1.f / zhi;
#pragma unroll
    for (int nt = 0; nt < 8; nt++) {
        int col = h * 64 + nt * 8 + 2 * tg;
        if (rlo < N_)
            *(unsigned*)(g_ao16 + ((size_t)b * N_ + rlo) * 512 + col) =
                pack2(o[nt][0] * izlo + ob[nt][0], o[nt][1] * izlo + ob[nt][1]);
        if (rhi < N_)
            *(unsigned*)(g_ao16 + ((size_t)b * N_ + rhi) * 512 + col) =
                pack2(o[nt][2] * izhi + ob[nt][2], o[nt][3] * izhi + ob[nt][3]);
    }
#undef FL_ISSUE
}

// ================= launch =================
extern "C" void kernel_launch(void* const* d_in, const int* in_sizes, int n_in,
                              void* d_out, int out_size) {
    const float* x         = (const float*)d_in[0];
    const float* W_qk      = (const float*)d_in[1];
    const float* W_v       = (const float*)d_in[2];
    const float* W_out     = (const float*)d_in[3];
    const float* b_out     = (const float*)d_in[4];
    const float* rel_bias  = (const float*)d_in[5];
    const float* ema_delta = (const float*)d_in[6];
    const float* ema_alpha = (const float*)d_in[7];
    const float* ema_beta  = (const float*)d_in[8];
    const float* ema_gamma = (const float*)d_in[9];
    const float* ema_omega = (const float*)d_in[10];
    float* out = (float*)d_out;

    static int attr_set = 0;
    if (!attr_set) {
        cudaFuncSetAttribute(ema_fused, cudaFuncAttributeMaxDynamicSharedMemorySize,
                             ESM_TOTAL * (int)sizeof(float));
        cudaFuncSetAttribute(gemm_qkv_tc, cudaFuncAttributeMaxDynamicSharedMemorySize, GSMEM_BYTES);
        cudaFuncSetAttribute(gemm_out_tc, cudaFuncAttributeMaxDynamicSharedMemorySize, GSMEM16_BYTES);
        cudaFuncSetAttribute(flash_attn_tc, cudaFuncAttributeMaxDynamicSharedMemorySize,
                             FSMEM_FLOATS * (int)sizeof(float));
        attr_set = 1;
    }

    coef_kernel<<<(2 * DIM_ * NDIM_ + 255) / 256, 256>>>(ema_delta, ema_alpha, ema_beta, ema_gamma);
    wcvt_kernel<<<(512 * 1024 + 255) / 256, 256>>>(W_qk, W_v);
    tcvt_simple<<<(512 * 512 + 255) / 256, 256>>>(W_out);
    ema_fused<<<dim3(DIM_ / 16, 1, B_), 256, ESM_TOTAL * sizeof(float)>>>(x, ema_omega);

    gemm_qkv_tc<<<GEMM_GRID, 128, GSMEM_BYTES>>>();

    flash_attn_tc<<<dim3((N_ + QROWS - 1) / QROWS, HEADS_, B_), 192,
                    FSMEM_FLOATS * sizeof(float)>>>(rel_bias);

    gemm_out_tc<<<GEMM_GRID, 128, GSMEM16_BYTES>>>(b_out, out);
}

// round 13
// speedup vs baseline: 1.2153x; 1.1126x over previous
#include <cuda_runtime.h>
#include <cuda_fp16.h>

#define B_     32
#define N_     577
#define L_     576
#define DIM_   512
#define HEADS_ 8
#define NDIM_  16
#define M_ROWS (B_ * N_)   // 18464
#define ECH 16
#define ECL 36

// -------- scratch (device globals; __half arrays 16B-aligned for cp.async) --------
// RULE (hard-learned): NEVER pass these as host-side kernel arguments — host code
// sees the shadow symbol address, not the device address. Reference them only
// from device code.
__device__ __align__(16) __half g_xm16[(size_t)B_ * N_ * DIM_];   // EMA out (fp16)
__device__ float g_qk[(size_t)B_ * N_ * 1024];                    // q|k fp32 (tf32-rounded)
__device__ float g_v [(size_t)B_ * N_ * 512];                     // v fp32 (tf32-rounded)
__device__ __align__(16) __half g_ao16[(size_t)B_ * N_ * 512];    // attn out (fp16)
__device__ float g_cq[NDIM_][2 * DIM_];
__device__ float g_cc[NDIM_][2 * DIM_];
__device__ __align__(16) __half g_wqk16[1024 * 512];              // W_qk^T [n][k] fp16
__device__ __align__(16) __half g_wv16 [512 * 512];               // W_v^T  [n][k] fp16
__device__ __align__(16) __half g_wo16 [512 * 512];               // W_out^T[n][k] fp16

// ---------------- helpers ----------------
__device__ __forceinline__ unsigned f2tf(float x) {
    unsigned u;
    asm("cvt.rna.tf32.f32 %0, %1;" : "=r"(u) : "f"(x));
    return u;
}
__device__ __forceinline__ float f2tff(float x) { return __uint_as_float(f2tf(x)); }
__device__ __forceinline__ unsigned pack2(float x, float y) {
    __half2 h = __floats2half2_rn(x, y);
    return *reinterpret_cast<unsigned*>(&h);
}
__device__ __forceinline__ void mma8(float* c, const unsigned* a, unsigned b0, unsigned b1) {
    asm volatile(
        "mma.sync.aligned.m16n8k8.row.col.f32.tf32.tf32.f32 "
        "{%0,%1,%2,%3},{%4,%5,%6,%7},{%8,%9},{%0,%1,%2,%3};"
        : "+f"(c[0]), "+f"(c[1]), "+f"(c[2]), "+f"(c[3])
        : "r"(a[0]), "r"(a[1]), "r"(a[2]), "r"(a[3]), "r"(b0), "r"(b1));
}
__device__ __forceinline__ void mma16(float* c, const unsigned* a, unsigned b0, unsigned b1) {
    asm volatile(
        "mma.sync.aligned.m16n8k16.row.col.f32.f16.f16.f32 "
        "{%0,%1,%2,%3},{%4,%5,%6,%7},{%8,%9},{%0,%1,%2,%3};"
        : "+f"(c[0]), "+f"(c[1]), "+f"(c[2]), "+f"(c[3])
        : "r"(a[0]), "r"(a[1]), "r"(a[2]), "r"(a[3]), "r"(b0), "r"(b1));
}
__device__ __forceinline__ unsigned s2u(const void* p) {
    return (unsigned)__cvta_generic_to_shared(p);
}
__device__ __forceinline__ void cp16(unsigned dst, const void* src, int srcsz) {
    asm volatile("cp.async.cg.shared.global [%0], [%1], 16, %2;"
                 :: "r"(dst), "l"(src), "r"(srcsz));
}
#define CP_COMMIT() asm volatile("cp.async.commit_group;")
#define CP_WAIT1()  asm volatile("cp.async.wait_group 1;")

__device__ __forceinline__ float pow36f(float q) {
    float q2 = q * q, q4 = q2 * q2, q8 = q4 * q4, q16 = q8 * q8, q32 = q16 * q16;
    return q32 * q4;
}

// ================= Stage 0: EMA coefficients + weight prep =================
__global__ void coef_kernel(const float* __restrict__ delta, const float* __restrict__ alpha,
                            const float* __restrict__ beta,  const float* __restrict__ gamma) {
    int idx = blockIdx.x * blockDim.x + threadIdx.x;
    if (idx >= 2 * DIM_ * NDIM_) return;
    int d = idx / NDIM_;
    int n = idx % NDIM_;
    float p  = 1.f / (1.f + expf(-delta[idx]));
    float sa = 1.f / (1.f + expf(-alpha[idx]));
    g_cq[n][d] = 1.f - p * sa;
    g_cc[n][d] = p * beta[idx] * gamma[idx] * 0.25f;
}

// W [512][Nn] f32 (k-major) -> global fp16 [Nn][512], selected INSIDE device code.
__global__ void tcvt_kernel(const float* __restrict__ src, int which, int Nn, int total) {
    int i = blockIdx.x * 256 + threadIdx.x;
    if (i >= total) return;
    int n = i >> 9, k = i & 511;
    __half v = __float2half_rn(src[(size_t)k * Nn + n]);
    if (which == 0)      g_wqk16[i] = v;
    else if (which == 1) g_wv16[i]  = v;
    else                 g_wo16[i]  = v;
}

// ================= Stage 1: fused bidirectional EMA (fp16 output) =========
#define ESM_STATE (ECH * NDIM_ * 17)
#define ESM_Y     (ECL * ECH * 17)
#define ESM_TOTAL (2 * ESM_STATE + ESM_Y)

__global__ void __launch_bounds__(256, 2) ema_fused(const float* __restrict__ x,
                                                    const float* __restrict__ omega) {
    extern __shared__ float es[];
    float* Sf = es;
    float* Sb = es + ESM_STATE;
    float* Ys = es + 2 * ESM_STATE;

    int tid = threadIdx.x;
    int c = tid >> 4, dl = tid & 15;
    int d = blockIdx.x * 16 + dl;
    int b = blockIdx.z;
    const float* xb = x + (size_t)b * N_ * DIM_ + d;
    __half*      yb = g_xm16 + (size_t)b * N_ * DIM_ + d;
    int t0 = c * ECL;

    if (tid < 16) yb[0] = __float2half_rn(xb[0]);   // cls token passthrough

    float q[NDIM_], q2[NDIM_], s[NDIM_];
#pragma unroll
    for (int n = 0; n < NDIM_; n++) { q[n] = g_cq[n][d]; s[n] = 0.f; }
#pragma unroll 4
    for (int tl = 0; tl < ECL; tl++) {
        float xv = xb[(size_t)(t0 + tl + 1) * DIM_];
#pragma unroll
        for (int n = 0; n < NDIM_; n++) s[n] = q[n] * s[n] + xv;
    }
#pragma unroll
    for (int n = 0; n < NDIM_; n++) Sf[(c * NDIM_ + n) * 17 + dl] = s[n];

#pragma unroll
    for (int n = 0; n < NDIM_; n++) { q2[n] = g_cq[n][d + DIM_]; s[n] = 0.f; }
#pragma unroll 4
    for (int tl = ECL - 1; tl >= 0; tl--) {
        float xv = xb[(size_t)(t0 + tl + 1) * DIM_];
#pragma unroll
        for (int n = 0; n < NDIM_; n++) s[n] = q2[n] * s[n] + xv;
    }
#pragma unroll
    for (int n = 0; n < NDIM_; n++) Sb[(c * NDIM_ + n) * 17 + dl] = s[n];
    __syncthreads();

    float cc[NDIM_];
#pragma unroll
    for (int n = 0; n < NDIM_; n++) {
        float qp = pow36f(q[n]);
        float Sin = 0.f;
        for (int cp = 0; cp < c; cp++)
            Sin = qp * Sin + Sf[(cp * NDIM_ + n) * 17 + dl];
        s[n] = Sin;
        cc[n] = g_cc[n][d];
    }
#pragma unroll 4
    for (int tl = 0; tl < ECL; tl++) {
        float xv = xb[(size_t)(t0 + tl + 1) * DIM_];
        float a[4] = {0.f, 0.f, 0.f, 0.f};
#pragma unroll
        for (int n = 0; n < NDIM_; n++) { s[n] = q[n] * s[n] + xv; a[n >> 2] += cc[n] * s[n]; }
        Ys[tl * (ECH * 17) + c * 17 + dl] = (a[0] + a[1]) + (a[2] + a[3]);
    }

#pragma unroll
    for (int n = 0; n < NDIM_; n++) {
        float qp = pow36f(q2[n]);
        float Sin = 0.f;
        for (int cp = ECH - 1; cp > c; cp--)
            Sin = qp * Sin + Sb[(cp * NDIM_ + n) * 17 + dl];
        s[n] = Sin;
        cc[n] = g_cc[n][d + DIM_];
    }
    float om = omega[d];
#pragma unroll 4
    for (int tl = ECL - 1; tl >= 0; tl--) {
        float xv = xb[(size_t)(t0 + tl + 1) * DIM_];
        float a[4] = {0.f, 0.f, 0.f, 0.f};
#pragma unroll
        for (int n = 0; n < NDIM_; n++) { s[n] = q2[n] * s[n] + xv; a[n >> 2] += cc[n] * s[n]; }
        float u = Ys[tl * (ECH * 17) + c * 17 + dl]
                + ((a[0] + a[1]) + (a[2] + a[3])) + xv * om;
        yb[(size_t)(t0 + tl + 1) * DIM_] = __float2half_rn(u / (1.f + __expf(-u)));
    }
}

// ======= fp16 GEMM (validated core): 128x128 tile, 2-stage cp.async, persistent =====
#define AWSTR 20
#define TSLAB (128 * AWSTR)
#define GSMEM16_BYTES (4 * TSLAB * 4)   // 40960 B

__device__ __forceinline__ void gemm16_tile(const __half* __restrict__ A,
                                            const __half* __restrict__ Bw, int M,
                                            float* __restrict__ C, int Cs,
                                            const float* __restrict__ bias, bool rnd,
                                            int bnb, int bmb) {
    extern __shared__ unsigned gsw[];
    unsigned* Asm = gsw;
    unsigned* Bsm = gsw + 2 * TSLAB;
    unsigned as_u = s2u(Asm), bs_u = s2u(Bsm);

    int tid = threadIdx.x, lane = tid & 31, w = tid >> 5;
    int gr = lane >> 2, tg = lane & 3;
    int wm = w & 1, wn = w >> 1;
    int bm = bmb * 128, bn = bnb * 128;

#define G16_ISSUE(s)                                                                   \
    do {                                                                               \
        int _buf = (s) & 1, _k0 = (s) * 32;                                            \
        unsigned _ad = as_u + (unsigned)(_buf * TSLAB * 4);                            \
        unsigned _bd = bs_u + (unsigned)(_buf * TSLAB * 4);                            \
        _Pragma("unroll")                                                              \
        for (int it = 0; it < 4; it++) {                                               \
            int idx = tid + it * 128;                                                  \
            int row = idx >> 2, cq = idx & 3;                                          \
            bool ok = (bm + row < M);                                                  \
            const __half* src = A + (size_t)(ok ? bm + row : 0) * 512 + _k0 + cq * 8;  \
            cp16(_ad + (unsigned)((row * AWSTR + cq * 4) * 4), src, ok ? 16 : 0);      \
        }                                                                              \
        _Pragma("unroll")                                                              \
        for (int it = 0; it < 4; it++) {                                               \
            int idx = tid + it * 128;                                                  \
            int row = idx >> 2, cq = idx & 3;                                          \
            cp16(_bd + (unsigned)((row * AWSTR + cq * 4) * 4),                         \
                 Bw + (size_t)(bn + row) * 512 + _k0 + cq * 8, 16);                    \
        }                                                                              \
    } while (0)

    G16_ISSUE(0); CP_COMMIT();

    float acc[4][8][4];
#pragma unroll
    for (int mt = 0; mt < 4; mt++)
#pragma unroll
        for (int nt = 0; nt < 8; nt++)
#pragma unroll
            for (int e = 0; e < 4; e++) acc[mt][nt][e] = 0.f;

    for (int s = 0; s < 16; s++) {
        __syncthreads();
        if (s + 1 < 16) G16_ISSUE(s + 1);
        CP_COMMIT();
        CP_WAIT1();
        __syncthreads();
        const unsigned* Ab = Asm + (s & 1) * TSLAB;
        const unsigned* Bb = Bsm + (s & 1) * TSLAB;
#pragma unroll
        for (int kk = 0; kk < 2; kk++) {
            unsigned a[4][4];
#pragma unroll
            for (int mt = 0; mt < 4; mt++) {
                int r = wm * 64 + mt * 16 + gr;
                int cw = kk * 8 + tg;
                a[mt][0] = Ab[r * AWSTR + cw];
                a[mt][1] = Ab[(r + 8) * AWSTR + cw];
                a[mt][2] = Ab[r * AWSTR + cw + 4];
                a[mt][3] = Ab[(r + 8) * AWSTR + cw + 4];
            }
            unsigned bf[8][2];
#pragma unroll
            for (int nt = 0; nt < 8; nt++) {
                int n = wn * 64 + nt * 8 + gr;
                bf[nt][0] = Bb[n * AWSTR + kk * 8 + tg];
                bf[nt][1] = Bb[n * AWSTR + kk * 8 + tg + 4];
            }
#pragma unroll
            for (int nt = 0; nt < 8; nt++)
#pragma unroll
                for (int mt = 0; mt < 4; mt++) mma16(acc[mt][nt], a[mt], bf[nt][0], bf[nt][1]);
        }
    }
#pragma unroll
    for (int mt = 0; mt < 4; mt++) {
        int r0 = bm + wm * 64 + mt * 16 + gr;
#pragma unroll
        for (int nt = 0; nt < 8; nt++) {
            int col = bn + wn * 64 + nt * 8 + 2 * tg;
            float bx = bias ? bias[col] : 0.f, by = bias ? bias[col + 1] : 0.f;
            float e0 = acc[mt][nt][0] + bx, e1 = acc[mt][nt][1] + by;
            float e2 = acc[mt][nt][2] + bx, e3 = acc[mt][nt][3] + by;
            if (rnd) { e0 = f2tff(e0); e1 = f2tff(e1); e2 = f2tff(e2); e3 = f2tff(e3); }
            if (r0 < M)     *(float2*)(C + (size_t)r0 * Cs + col)       = make_float2(e0, e1);
            if (r0 + 8 < M) *(float2*)(C + (size_t)(r0 + 8) * Cs + col) = make_float2(e2, e3);
        }
    }
#undef G16_ISSUE
}

#define MB_ ((M_ROWS + 127) / 128)   // 145
#define GEMM_GRID 444

__global__ void __launch_bounds__(128, 3) gemm_qkv_tc() {
    for (int t = blockIdx.x; t < MB_ * 12; t += GEMM_GRID) {
        if (t < MB_ * 8)
            gemm16_tile(g_xm16, g_wqk16, M_ROWS, g_qk, 1024, nullptr, true, t & 7, t >> 3);
        else {
            int tt = t - MB_ * 8;
            gemm16_tile(g_xm16, g_wv16, M_ROWS, g_v, 512, nullptr, true, tt & 3, tt >> 2);
        }
    }
}
__global__ void __launch_bounds__(128, 3) gemm_out_tc(const float* __restrict__ bias,
                                                      float* __restrict__ out) {
    for (int t = blockIdx.x; t < MB_ * 4; t += GEMM_GRID)
        gemm16_tile(g_ao16, g_wo16, M_ROWS, out, 512, bias, false, t & 3, t >> 2);
}

// ================= Stage 3: flash attention (tf32, round-11 verbatim) ====
#define KSTR 68
#define VSTR 72
#define PSTR 68
#define QROWS 96
#define KBUF (64 * KSTR)
#define VBUF (64 * VSTR)
#define NT_ ((N_ + 63) / 64)
#define FSMEM_FLOATS (2 * KBUF + 2 * VBUF + QROWS * PSTR + (2 * N_ - 1))

__global__ void __launch_bounds__(192, 2) flash_attn_tc(const float* __restrict__ rb) {
    extern __shared__ float sm[];
    float* Ks  = sm;
    float* Vs  = sm + 2 * KBUF;
    float* Ps  = sm + 2 * KBUF + 2 * VBUF;
    float* RBs = Ps + QROWS * PSTR;
    unsigned ks_u = s2u(Ks), vs_u = s2u(Vs);

    int b = blockIdx.z, h = blockIdx.y;
    int i0 = blockIdx.x * QROWS;
    int tid = threadIdx.x, lane = tid & 31, w = tid >> 5;
    int gr = lane >> 2, tg = lane & 3;

    const float* qb = g_qk + (size_t)b * N_ * 1024 + h * 64;
    const float* kb = qb + 512;
    const float* vb = g_v + (size_t)b * N_ * 512 + h * 64;

    for (int t = tid; t < 2 * N_ - 1; t += 192) RBs[t] = rb[t];

#define FL_ISSUE(jt)                                                                   \
    do {                                                                               \
        int _buf = (jt) & 1, _j0 = (jt) * 64;                                          \
        unsigned _kd = ks_u + (unsigned)(_buf * KBUF * 4);                             \
        unsigned _vd = vs_u + (unsigned)(_buf * VBUF * 4);                             \
        for (int idx = tid; idx < 1024; idx += 192) {                                  \
            int row = idx >> 4, cq = (idx & 15) * 4;                                   \
            int j = _j0 + row;                                                         \
            bool ok = (j < N_);                                                        \
            int js = ok ? j : 0;                                                       \
            cp16(_kd + (unsigned)((row * KSTR + cq) * 4),                              \
                 kb + (size_t)js * 1024 + cq, ok ? 16 : 0);                            \
            cp16(_vd + (unsigned)((row * VSTR + cq) * 4),                              \
                 vb + (size_t)js * 512 + cq, ok ? 16 : 0);                             \
        }                                                                              \
    } while (0)

    unsigned qa[8][4];
    int rlo = i0 + w * 16 + gr;
    int rhi = rlo + 8;
#pragma unroll
    for (int kk = 0; kk < 8; kk++) {
        int c0 = kk * 8 + tg;
        float v0 = (rlo < N_) ? 0.125f * qb[(size_t)rlo * 1024 + c0]     : 0.f;
        float v1 = (rhi < N_) ? 0.125f * qb[(size_t)rhi * 1024 + c0]     : 0.f;
        float v2 = (rlo < N_) ? 0.125f * qb[(size_t)rlo * 1024 + c0 + 4] : 0.f;
        float v3 = (rhi < N_) ? 0.125f * qb[(size_t)rhi * 1024 + c0 + 4] : 0.f;
        qa[kk][0] = __float_as_uint(v0); qa[kk][1] = __float_as_uint(v1);
        qa[kk][2] = __float_as_uint(v2); qa[kk][3] = __float_as_uint(v3);
    }

    FL_ISSUE(0); CP_COMMIT();

    float o[8][4], ob[8][4];
#pragma unroll
    for (int nt = 0; nt < 8; nt++)
#pragma unroll
        for (int e = 0; e < 4; e++) { o[nt][e] = 0.f; ob[nt][e] = 0.f; }
    float mlo = -1e30f, mhi = -1e30f, zlo = 0.f, zhi = 0.f;

    for (int jt = 0; jt < NT_; jt++) {
        int j0 = jt * 64;
        bool full = (j0 + 64 <= N_);
        __syncthreads();
        if (jt + 1 < NT_) FL_ISSUE(jt + 1);
        CP_COMMIT();
        CP_WAIT1();
        __syncthreads();
        const float* Ksb = Ks + (jt & 1) * KBUF;
        const float* Vsb = Vs + (jt & 1) * VBUF;

        float s[8][4];
#pragma unroll
        for (int nt = 0; nt < 8; nt++) {
#pragma unroll
            for (int e = 0; e < 4; e++) s[nt][e] = 0.f;
#pragma unroll
            for (int kk = 0; kk < 8; kk++) {
                unsigned b0 = __float_as_uint(Ksb[(nt * 8 + gr) * KSTR + kk * 8 + tg]);
                unsigned b1 = __float_as_uint(Ksb[(nt * 8 + gr) * KSTR + kk * 8 + tg + 4]);
                mma8(s[nt], qa[kk], b0, b1);
            }
        }

        float tlo = -1e30f, thi = -1e30f;
#pragma unroll
        for (int nt = 0; nt < 8; nt++) {
            int col = j0 + nt * 8 + 2 * tg;
            if (full || col < N_)     { tlo = fmaxf(tlo, s[nt][0]); thi = fmaxf(thi, s[nt][2]); }
            if (full || col + 1 < N_) { tlo = fmaxf(tlo, s[nt][1]); thi = fmaxf(thi, s[nt][3]); }
        }
#pragma unroll
        for (int off = 1; off <= 2; off <<= 1) {
            tlo = fmaxf(tlo, __shfl_xor_sync(0xffffffffu, tlo, off));
            thi = fmaxf(thi, __shfl_xor_sync(0xffffffffu, thi, off));
        }
        float mlon = fmaxf(mlo, tlo), mhin = fmaxf(mhi, thi);
        float sclo = __expf(mlo - mlon), schi = __expf(mhi - mhin);
        float psl = 0.f, psh = 0.f;
        int prow_lo = (w * 16 + gr) * PSTR;
        int prow_hi = (w * 16 + gr + 8) * PSTR;
#pragma unroll
        for (int nt = 0; nt < 8; nt++) {
            int col = j0 + nt * 8 + 2 * tg;
            float p0 = (full || col     < N_) ? __expf(s[nt][0] - mlon) : 0.f;
            float p1 = (full || col + 1 < N_) ? __expf(s[nt][1] - mlon) : 0.f;
            float p2 = (full || col     < N_) ? __expf(s[nt][2] - mhin) : 0.f;
            float p3 = (full || col + 1 < N_) ? __expf(s[nt][3] - mhin) : 0.f;
            psl += p0 + p1; psh += p2 + p3;
            o[nt][0] *= sclo; o[nt][1] *= sclo;
            o[nt][2] *= schi; o[nt][3] *= schi;
            *(float2*)(Ps + prow_lo + nt * 8 + 2 * tg) = make_float2(f2tff(p0), f2tff(p1));
            *(float2*)(Ps + prow_hi + nt * 8 + 2 * tg) = make_float2(f2tff(p2), f2tff(p3));
        }
#pragma unroll
        for (int off = 1; off <= 2; off <<= 1) {
            psl += __shfl_xor_sync(0xffffffffu, psl, off);
            psh += __shfl_xor_sync(0xffffffffu, psh, off);
        }
        zlo = zlo * sclo + psl;  zhi = zhi * schi + psh;
        mlo = mlon;  mhi = mhin;
        __syncwarp();

#pragma unroll
        for (int kk = 0; kk < 8; kk++) {
            unsigned pa[4], ba[4];
            int pc = kk * 8 + tg;
            pa[0] = __float_as_uint(Ps[prow_lo + pc]);
            pa[1] = __float_as_uint(Ps[prow_hi + pc]);
            pa[2] = __float_as_uint(Ps[prow_lo + pc + 4]);
            pa[3] = __float_as_uint(Ps[prow_hi + pc + 4]);
            int jlo = j0 + kk * 8 + tg, jhi = jlo + 4;
            float b00 = (rlo < N_ && jlo < N_) ? RBs[576 + jlo - rlo] : 0.f;
            float b01 = (rhi < N_ && jlo < N_) ? RBs[576 + jlo - rhi] : 0.f;
            float b02 = (rlo < N_ && jhi < N_) ? RBs[576 + jhi - rlo] : 0.f;
            float b03 = (rhi < N_ && jhi < N_) ? RBs[576 + jhi - rhi] : 0.f;
            ba[0] = f2tf(b00); ba[1] = f2tf(b01); ba[2] = f2tf(b02); ba[3] = f2tf(b03);
#pragma unroll
            for (int nt = 0; nt < 8; nt++) {
                unsigned v0 = __float_as_uint(Vsb[(kk * 8 + tg) * VSTR + nt * 8 + gr]);
                unsigned v1 = __float_as_uint(Vsb[(kk * 8 + tg + 4) * VSTR + nt * 8 + gr]);
                mma8(o[nt],  pa, v0, v1);
                mma8(ob[nt], ba, v0, v1);
            }
        }
        __syncwarp();
    }

    // ---- epilogue: (O/Z + Ob) -> fp16 g_ao16 ----
    float izlo = 1.f / zlo, izhi = 1.f / zhi;
#pragma unroll
    for (int nt = 0; nt < 8; nt++) {
        int col = h * 64 + nt * 8 + 2 * tg;
        if (rlo < N_)
            *(unsigned*)(g_ao16 + ((size_t)b * N_ + rlo) * 512 + col) =
                pack2(o[nt][0] * izlo + ob[nt][0], o[nt][1] * izlo + ob[nt][1]);
        if (rhi < N_)
            *(unsigned*)(g_ao16 + ((size_t)b * N_ + rhi) * 512 + col) =
                pack2(o[nt][2] * izhi + ob[nt][2], o[nt][3] * izhi + ob[nt][3]);
    }
#undef FL_ISSUE
}

// ================= launch =================
extern "C" void kernel_launch(void* const* d_in, const int* in_sizes, int n_in,
                              void* d_out, int out_size) {
    const float* x         = (const float*)d_in[0];
    const float* W_qk      = (const float*)d_in[1];
    const float* W_v       = (const float*)d_in[2];
    const float* W_out     = (const float*)d_in[3];
    const float* b_out     = (const float*)d_in[4];
    const float* rel_bias  = (const float*)d_in[5];
    const float* ema_delta = (const float*)d_in[6];
    const float* ema_alpha = (const float*)d_in[7];
    const float* ema_beta  = (const float*)d_in[8];
    const float* ema_gamma = (const float*)d_in[9];
    const float* ema_omega = (const float*)d_in[10];
    float* out = (float*)d_out;

    static int attr_set = 0;
    if (!attr_set) {
        cudaFuncSetAttribute(ema_fused, cudaFuncAttributeMaxDynamicSharedMemorySize,
                             ESM_TOTAL * (int)sizeof(float));
        cudaFuncSetAttribute(gemm_qkv_tc, cudaFuncAttributeMaxDynamicSharedMemorySize, GSMEM16_BYTES);
        cudaFuncSetAttribute(gemm_out_tc, cudaFuncAttributeMaxDynamicSharedMemorySize, GSMEM16_BYTES);
        cudaFuncSetAttribute(flash_attn_tc, cudaFuncAttributeMaxDynamicSharedMemorySize,
                             FSMEM_FLOATS * (int)sizeof(float));
        attr_set = 1;
    }

    coef_kernel<<<(2 * DIM_ * NDIM_ + 255) / 256, 256>>>(ema_delta, ema_alpha, ema_beta, ema_gamma);
    tcvt_kernel<<<(1024 * 512 + 255) / 256, 256>>>(W_qk, 0, 1024, 1024 * 512);
    tcvt_kernel<<<(512 * 512 + 255) / 256, 256>>>(W_v, 1, 512, 512 * 512);
    tcvt_kernel<<<(512 * 512 + 255) / 256, 256>>>(W_out, 2, 512, 512 * 512);
    ema_fused<<<dim3(DIM_ / 16, 1, B_), 256, ESM_TOTAL * sizeof(float)>>>(x, ema_omega);

    gemm_qkv_tc<<<GEMM_GRID, 128, GSMEM16_BYTES>>>();

    flash_attn_tc<<<dim3((N_ + QROWS - 1) / QROWS, HEADS_, B_), 192,
                    FSMEM_FLOATS * sizeof(float)>>>(rel_bias);

    gemm_out_tc<<<GEMM_GRID, 128, GSMEM16_BYTES>>>(b_out, out);
}

// round 14
// speedup vs baseline: 1.4807x; 1.2184x over previous
#include <cuda_runtime.h>
#include <cuda_fp16.h>

#define B_     32
#define N_     577
#define L_     576
#define DIM_   512
#define HEADS_ 8
#define NDIM_  16
#define M_ROWS (B_ * N_)   // 18464
#define ECH 16
#define ECL 36
#define VTP 640            // padded j-extent of V^T (mult of 8, >= 577+63)

// -------- scratch (device globals; __half arrays 16B-aligned for cp.async) --------
// RULE: NEVER pass these as host-side kernel arguments (host shadow symbol!).
__device__ __align__(16) __half g_xm16[(size_t)B_ * N_ * DIM_];   // EMA out (fp16)
__device__ __align__(16) __half g_qk16[(size_t)B_ * N_ * 1024];   // q|k fp16
__device__ float g_v [(size_t)B_ * N_ * 512];                     // v fp32
__device__ __align__(16) __half g_vt16[(size_t)B_ * 512 * VTP];   // V^T fp16, j-padded
__device__ __align__(16) __half g_ao16[(size_t)B_ * N_ * 512];    // attn out (fp16)
__device__ float g_cq[NDIM_][2 * DIM_];
__device__ float g_cc[NDIM_][2 * DIM_];
__device__ __align__(16) __half g_wqk16[1024 * 512];              // W_qk^T [n][k] fp16
__device__ __align__(16) __half g_wv16 [512 * 512];               // W_v^T  [n][k] fp16
__device__ __align__(16) __half g_wo16 [512 * 512];               // W_out^T[n][k] fp16

// ---------------- helpers ----------------
__device__ __forceinline__ unsigned f2tf(float x) {
    unsigned u;
    asm("cvt.rna.tf32.f32 %0, %1;" : "=r"(u) : "f"(x));
    return u;
}
__device__ __forceinline__ float f2tff(float x) { return __uint_as_float(f2tf(x)); }
__device__ __forceinline__ unsigned pack2(float x, float y) {
    __half2 h = __floats2half2_rn(x, y);
    return *reinterpret_cast<unsigned*>(&h);
}
__device__ __forceinline__ void mma16(float* c, const unsigned* a, unsigned b0, unsigned b1) {
    asm volatile(
        "mma.sync.aligned.m16n8k16.row.col.f32.f16.f16.f32 "
        "{%0,%1,%2,%3},{%4,%5,%6,%7},{%8,%9},{%0,%1,%2,%3};"
        : "+f"(c[0]), "+f"(c[1]), "+f"(c[2]), "+f"(c[3])
        : "r"(a[0]), "r"(a[1]), "r"(a[2]), "r"(a[3]), "r"(b0), "r"(b1));
}
__device__ __forceinline__ unsigned s2u(const void* p) {
    return (unsigned)__cvta_generic_to_shared(p);
}
__device__ __forceinline__ void cp16(unsigned dst, const void* src, int srcsz) {
    asm volatile("cp.async.cg.shared.global [%0], [%1], 16, %2;"
                 :: "r"(dst), "l"(src), "r"(srcsz));
}
#define CP_COMMIT() asm volatile("cp.async.commit_group;")
#define CP_WAIT1()  asm volatile("cp.async.wait_group 1;")

__device__ __forceinline__ float pow36f(float q) {
    float q2 = q * q, q4 = q2 * q2, q8 = q4 * q4, q16 = q8 * q8, q32 = q16 * q16;
    return q32 * q4;
}

// ================= Stage 0: EMA coefficients + weight prep =================
__global__ void coef_kernel(const float* __restrict__ delta, const float* __restrict__ alpha,
                            const float* __restrict__ beta,  const float* __restrict__ gamma) {
    int idx = blockIdx.x * blockDim.x + threadIdx.x;
    if (idx >= 2 * DIM_ * NDIM_) return;
    int d = idx / NDIM_;
    int n = idx % NDIM_;
    float p  = 1.f / (1.f + expf(-delta[idx]));
    float sa = 1.f / (1.f + expf(-alpha[idx]));
    g_cq[n][d] = 1.f - p * sa;
    g_cc[n][d] = p * beta[idx] * gamma[idx] * 0.25f;
}

__global__ void tcvt_kernel(const float* __restrict__ src, int which, int Nn, int total) {
    int i = blockIdx.x * 256 + threadIdx.x;
    if (i >= total) return;
    int n = i >> 9, k = i & 511;
    __half v = __float2half_rn(src[(size_t)k * Nn + n]);
    if (which == 0)      g_wqk16[i] = v;
    else if (which == 1) g_wv16[i]  = v;
    else                 g_wo16[i]  = v;
}

// ================= Stage 1: fused bidirectional EMA (fp16 output) =========
#define ESM_STATE (ECH * NDIM_ * 17)
#define ESM_Y     (ECL * ECH * 17)
#define ESM_TOTAL (2 * ESM_STATE + ESM_Y)

__global__ void __launch_bounds__(256, 2) ema_fused(const float* __restrict__ x,
                                                    const float* __restrict__ omega) {
    extern __shared__ float es[];
    float* Sf = es;
    float* Sb = es + ESM_STATE;
    float* Ys = es + 2 * ESM_STATE;

    int tid = threadIdx.x;
    int c = tid >> 4, dl = tid & 15;
    int d = blockIdx.x * 16 + dl;
    int b = blockIdx.z;
    const float* xb = x + (size_t)b * N_ * DIM_ + d;
    __half*      yb = g_xm16 + (size_t)b * N_ * DIM_ + d;
    int t0 = c * ECL;

    if (tid < 16) yb[0] = __float2half_rn(xb[0]);

    float q[NDIM_], q2[NDIM_], s[NDIM_];
#pragma unroll
    for (int n = 0; n < NDIM_; n++) { q[n] = g_cq[n][d]; s[n] = 0.f; }
#pragma unroll 4
    for (int tl = 0; tl < ECL; tl++) {
        float xv = xb[(size_t)(t0 + tl + 1) * DIM_];
#pragma unroll
        for (int n = 0; n < NDIM_; n++) s[n] = q[n] * s[n] + xv;
    }
#pragma unroll
    for (int n = 0; n < NDIM_; n++) Sf[(c * NDIM_ + n) * 17 + dl] = s[n];

#pragma unroll
    for (int n = 0; n < NDIM_; n++) { q2[n] = g_cq[n][d + DIM_]; s[n] = 0.f; }
#pragma unroll 4
    for (int tl = ECL - 1; tl >= 0; tl--) {
        float xv = xb[(size_t)(t0 + tl + 1) * DIM_];
#pragma unroll
        for (int n = 0; n < NDIM_; n++) s[n] = q2[n] * s[n] + xv;
    }
#pragma unroll
    for (int n = 0; n < NDIM_; n++) Sb[(c * NDIM_ + n) * 17 + dl] = s[n];
    __syncthreads();

    float cc[NDIM_];
#pragma unroll
    for (int n = 0; n < NDIM_; n++) {
        float qp = pow36f(q[n]);
        float Sin = 0.f;
        for (int cp = 0; cp < c; cp++)
            Sin = qp * Sin + Sf[(cp * NDIM_ + n) * 17 + dl];
        s[n] = Sin;
        cc[n] = g_cc[n][d];
    }
#pragma unroll 4
    for (int tl = 0; tl < ECL; tl++) {
        float xv = xb[(size_t)(t0 + tl + 1) * DIM_];
        float a[4] = {0.f, 0.f, 0.f, 0.f};
#pragma unroll
        for (int n = 0; n < NDIM_; n++) { s[n] = q[n] * s[n] + xv; a[n >> 2] += cc[n] * s[n]; }
        Ys[tl * (ECH * 17) + c * 17 + dl] = (a[0] + a[1]) + (a[2] + a[3]);
    }

#pragma unroll
    for (int n = 0; n < NDIM_; n++) {
        float qp = pow36f(q2[n]);
        float Sin = 0.f;
        for (int cp = ECH - 1; cp > c; cp--)
            Sin = qp * Sin + Sb[(cp * NDIM_ + n) * 17 + dl];
        s[n] = Sin;
        cc[n] = g_cc[n][d + DIM_];
    }
    float om = omega[d];
#pragma unroll 4
    for (int tl = ECL - 1; tl >= 0; tl--) {
        float xv = xb[(size_t)(t0 + tl + 1) * DIM_];
        float a[4] = {0.f, 0.f, 0.f, 0.f};
#pragma unroll
        for (int n = 0; n < NDIM_; n++) { s[n] = q2[n] * s[n] + xv; a[n >> 2] += cc[n] * s[n]; }
        float u = Ys[tl * (ECH * 17) + c * 17 + dl]
                + ((a[0] + a[1]) + (a[2] + a[3])) + xv * om;
        yb[(size_t)(t0 + tl + 1) * DIM_] = __float2half_rn(u / (1.f + __expf(-u)));
    }
}

// ======= fp16 GEMM (validated): 128x128 tile, 2-stage cp.async, persistent =====
#define AWSTR 20
#define TSLAB (128 * AWSTR)
#define GSMEM16_BYTES (4 * TSLAB * 4)

__device__ __forceinline__ void gemm16_tile(const __half* __restrict__ A,
                                            const __half* __restrict__ Bw, int M,
                                            __half* __restrict__ C16, int c16s,
                                            float* __restrict__ C32, int c32s,
                                            const float* __restrict__ bias, bool rnd,
                                            int bnb, int bmb) {
    extern __shared__ unsigned gsw[];
    unsigned* Asm = gsw;
    unsigned* Bsm = gsw + 2 * TSLAB;
    unsigned as_u = s2u(Asm), bs_u = s2u(Bsm);

    int tid = threadIdx.x, lane = tid & 31, w = tid >> 5;
    int gr = lane >> 2, tg = lane & 3;
    int wm = w & 1, wn = w >> 1;
    int bm = bmb * 128, bn = bnb * 128;

#define G16_ISSUE(s)                                                                   \
    do {                                                                               \
        int _buf = (s) & 1, _k0 = (s) * 32;                                            \
        unsigned _ad = as_u + (unsigned)(_buf * TSLAB * 4);                            \
        unsigned _bd = bs_u + (unsigned)(_buf * TSLAB * 4);                            \
        _Pragma("unroll")                                                              \
        for (int it = 0; it < 4; it++) {                                               \
            int idx = tid + it * 128;                                                  \
            int row = idx >> 2, cq = idx & 3;                                          \
            bool ok = (bm + row < M);                                                  \
            const __half* src = A + (size_t)(ok ? bm + row : 0) * 512 + _k0 + cq * 8;  \
            cp16(_ad + (unsigned)((row * AWSTR + cq * 4) * 4), src, ok ? 16 : 0);      \
        }                                                                              \
        _Pragma("unroll")                                                              \
        for (int it = 0; it < 4; it++) {                                               \
            int idx = tid + it * 128;                                                  \
            int row = idx >> 2, cq = idx & 3;                                          \
            cp16(_bd + (unsigned)((row * AWSTR + cq * 4) * 4),                         \
                 Bw + (size_t)(bn + row) * 512 + _k0 + cq * 8, 16);                    \
        }                                                                              \
    } while (0)

    G16_ISSUE(0); CP_COMMIT();

    float acc[4][8][4];
#pragma unroll
    for (int mt = 0; mt < 4; mt++)
#pragma unroll
        for (int nt = 0; nt < 8; nt++)
#pragma unroll
            for (int e = 0; e < 4; e++) acc[mt][nt][e] = 0.f;

    for (int s = 0; s < 16; s++) {
        __syncthreads();
        if (s + 1 < 16) G16_ISSUE(s + 1);
        CP_COMMIT();
        CP_WAIT1();
        __syncthreads();
        const unsigned* Ab = Asm + (s & 1) * TSLAB;
        const unsigned* Bb = Bsm + (s & 1) * TSLAB;
#pragma unroll
        for (int kk = 0; kk < 2; kk++) {
            unsigned a[4][4];
#pragma unroll
            for (int mt = 0; mt < 4; mt++) {
                int r = wm * 64 + mt * 16 + gr;
                int cw = kk * 8 + tg;
                a[mt][0] = Ab[r * AWSTR + cw];
                a[mt][1] = Ab[(r + 8) * AWSTR + cw];
                a[mt][2] = Ab[r * AWSTR + cw + 4];
                a[mt][3] = Ab[(r + 8) * AWSTR + cw + 4];
            }
            unsigned bf[8][2];
#pragma unroll
            for (int nt = 0; nt < 8; nt++) {
                int n = wn * 64 + nt * 8 + gr;
                bf[nt][0] = Bb[n * AWSTR + kk * 8 + tg];
                bf[nt][1] = Bb[n * AWSTR + kk * 8 + tg + 4];
            }
#pragma unroll
            for (int nt = 0; nt < 8; nt++)
#pragma unroll
                for (int mt = 0; mt < 4; mt++) mma16(acc[mt][nt], a[mt], bf[nt][0], bf[nt][1]);
        }
    }
#pragma unroll
    for (int mt = 0; mt < 4; mt++) {
        int r0 = bm + wm * 64 + mt * 16 + gr;
#pragma unroll
        for (int nt = 0; nt < 8; nt++) {
            int col = bn + wn * 64 + nt * 8 + 2 * tg;
            if (C16) {
                if (r0 < M)
                    *(unsigned*)(C16 + (size_t)r0 * c16s + col) =
                        pack2(acc[mt][nt][0], acc[mt][nt][1]);
                if (r0 + 8 < M)
                    *(unsigned*)(C16 + (size_t)(r0 + 8) * c16s + col) =
                        pack2(acc[mt][nt][2], acc[mt][nt][3]);
            } else {
                float bx = bias ? bias[col] : 0.f, by = bias ? bias[col + 1] : 0.f;
                float e0 = acc[mt][nt][0] + bx, e1 = acc[mt][nt][1] + by;
                float e2 = acc[mt][nt][2] + bx, e3 = acc[mt][nt][3] + by;
                if (rnd) { e0 = f2tff(e0); e1 = f2tff(e1); e2 = f2tff(e2); e3 = f2tff(e3); }
                if (r0 < M)     *(float2*)(C32 + (size_t)r0 * c32s + col)       = make_float2(e0, e1);
                if (r0 + 8 < M) *(float2*)(C32 + (size_t)(r0 + 8) * c32s + col) = make_float2(e2, e3);
            }
        }
    }
#undef G16_ISSUE
}

#define MB_ ((M_ROWS + 127) / 128)   // 145
#define GEMM_GRID 444

__global__ void __launch_bounds__(128, 3) gemm_qkv_tc() {
    for (int t = blockIdx.x; t < MB_ * 12; t += GEMM_GRID) {
        if (t < MB_ * 8)
            gemm16_tile(g_xm16, g_wqk16, M_ROWS, g_qk16, 1024, nullptr, 0, nullptr, false,
                        t & 7, t >> 3);
        else {
            int tt = t - MB_ * 8;
            gemm16_tile(g_xm16, g_wv16, M_ROWS, nullptr, 0, g_v, 512, nullptr, true,
                        tt & 3, tt >> 2);
        }
    }
}
__global__ void __launch_bounds__(128, 3) gemm_out_tc(const float* __restrict__ bias,
                                                      float* __restrict__ out) {
    for (int t = blockIdx.x; t < MB_ * 4; t += GEMM_GRID)
        gemm16_tile(g_ao16, g_wo16, M_ROWS, nullptr, 0, out, 512, bias, false, t & 3, t >> 2);
}

// ===== Stage 2b: V transpose  g_v fp32 [b*N][512] -> g_vt16 fp16 [b][512][VTP] =====
__global__ void vt_kernel() {
    __shared__ float ts[32][33];
    int tx = threadIdx.x, ty = threadIdx.y;
    int n0 = blockIdx.x * 32, d0 = blockIdx.y * 32, b = blockIdx.z;
#pragma unroll
    for (int i = 0; i < 4; i++) {
        int n = n0 + ty + i * 8;
        ts[ty + i * 8][tx] = (n < N_) ? g_v[((size_t)b * N_ + n) * 512 + d0 + tx] : 0.f;
    }
    __syncthreads();
#pragma unroll
    for (int i = 0; i < 4; i++) {
        int d = d0 + ty + i * 8;
        g_vt16[((size_t)b * 512 + d) * VTP + n0 + tx] = __float2half_rn(ts[tx][ty + i * 8]);
    }
}

// ================= Stage 3: fp16 flash attention =================
// K tile [64 j][36 words], V^T tile [64 d][36 words]; frag bank 4*gr+tg+8kk: clean.
#define FKSTR 36
#define FKBUF (64 * FKSTR)                 // words per tile buffer
#define QROWS 96
#define NT_ ((N_ + 63) / 64)
#define FSMEM_BYTES (4 * FKBUF * 4 + (2 * N_ - 1) * 4)

__global__ void __launch_bounds__(192, 2) flash_attn_tc(const float* __restrict__ rb) {
    extern __shared__ unsigned fsw[];
    unsigned* Ksw = fsw;                   // [2][FKBUF]
    unsigned* Vsw = fsw + 2 * FKBUF;       // [2][FKBUF]
    float*    RBs = (float*)(fsw + 4 * FKBUF);
    unsigned ks_u = s2u(Ksw), vs_u = s2u(Vsw);

    int b = blockIdx.z, h = blockIdx.y;
    int i0 = blockIdx.x * QROWS;
    int tid = threadIdx.x, lane = tid & 31, w = tid >> 5;
    int gr = lane >> 2, tg = lane & 3;

    const __half* kb16 = g_qk16 + (size_t)b * N_ * 1024 + 512 + h * 64;
    const __half* vtb  = g_vt16 + ((size_t)b * 512 + h * 64) * VTP;
    const unsigned* qw = (const unsigned*)g_qk16 + (size_t)b * N_ * 512 + h * 32;

    for (int t = tid; t < 2 * N_ - 1; t += 192) RBs[t] = rb[t];

#define FL_ISSUE(jt)                                                                   \
    do {                                                                               \
        int _buf = (jt) & 1, _j0 = (jt) * 64;                                          \
        unsigned _kd = ks_u + (unsigned)(_buf * FKBUF * 4);                            \
        unsigned _vd = vs_u + (unsigned)(_buf * FKBUF * 4);                            \
        for (int idx = tid; idx < 512; idx += 192) {                                   \
            int j = idx >> 3, ch = idx & 7;                                            \
            bool ok = (_j0 + j < N_);                                                  \
            cp16(_kd + (unsigned)((j * FKSTR + ch * 4) * 4),                           \
                 kb16 + (size_t)(ok ? _j0 + j : 0) * 1024 + ch * 8, ok ? 16 : 0);      \
        }                                                                              \
        for (int idx = tid; idx < 512; idx += 192) {                                   \
            int dd = idx >> 3, ch = idx & 7;                                           \
            cp16(_vd + (unsigned)((dd * FKSTR + ch * 4) * 4),                          \
                 vtb + (size_t)dd * VTP + _j0 + ch * 8, 16);                           \
        }                                                                              \
    } while (0)

    // Q fragments (fp16 words straight from g_qk16)
    unsigned qa[4][4];
    int rlo = i0 + w * 16 + gr;
    int rhi = rlo + 8;
#pragma unroll
    for (int kk = 0; kk < 4; kk++) {
        qa[kk][0] = (rlo < N_) ? qw[(size_t)rlo * 512 + kk * 8 + tg]     : 0u;
        qa[kk][1] = (rhi < N_) ? qw[(size_t)rhi * 512 + kk * 8 + tg]     : 0u;
        qa[kk][2] = (rlo < N_) ? qw[(size_t)rlo * 512 + kk * 8 + tg + 4] : 0u;
        qa[kk][3] = (rhi < N_) ? qw[(size_t)rhi * 512 + kk * 8 + tg + 4] : 0u;
    }

    FL_ISSUE(0); CP_COMMIT();

    float o[8][4], ob[8][4];
#pragma unroll
    for (int nt = 0; nt < 8; nt++)
#pragma unroll
        for (int e = 0; e < 4; e++) { o[nt][e] = 0.f; ob[nt][e] = 0.f; }
    float mlo = -1e30f, mhi = -1e30f, zlo = 0.f, zhi = 0.f;

    for (int jt = 0; jt < NT_; jt++) {
        int j0 = jt * 64;
        bool full = (j0 + 64 <= N_);
        __syncthreads();
        if (jt + 1 < NT_) FL_ISSUE(jt + 1);
        CP_COMMIT();
        CP_WAIT1();
        __syncthreads();
        const unsigned* Kb = Ksw + (jt & 1) * FKBUF;
        const unsigned* Vb = Vsw + (jt & 1) * FKBUF;

        // ---- S = (Q @ K^T) * 0.125 ----
        float s[8][4];
#pragma unroll
        for (int nt = 0; nt < 8; nt++) {
#pragma unroll
            for (int e = 0; e < 4; e++) s[nt][e] = 0.f;
#pragma unroll
            for (int kk = 0; kk < 4; kk++) {
                unsigned b0 = Kb[(nt * 8 + gr) * FKSTR + kk * 8 + tg];
                unsigned b1 = Kb[(nt * 8 + gr) * FKSTR + kk * 8 + tg + 4];
                mma16(s[nt], qa[kk], b0, b1);
            }
#pragma unroll
            for (int e = 0; e < 4; e++) s[nt][e] *= 0.125f;
        }

        // ---- online softmax; P packed straight into fp16 A-frag words ----
        float tlo = -1e30f, thi = -1e30f;
#pragma unroll
        for (int nt = 0; nt < 8; nt++) {
            int col = j0 + nt * 8 + 2 * tg;
            if (full || col < N_)     { tlo = fmaxf(tlo, s[nt][0]); thi = fmaxf(thi, s[nt][2]); }
            if (full || col + 1 < N_) { tlo = fmaxf(tlo, s[nt][1]); thi = fmaxf(thi, s[nt][3]); }
        }
#pragma unroll
        for (int off = 1; off <= 2; off <<= 1) {
            tlo = fmaxf(tlo, __shfl_xor_sync(0xffffffffu, tlo, off));
            thi = fmaxf(thi, __shfl_xor_sync(0xffffffffu, thi, off));
        }
        float mlon = fmaxf(mlo, tlo), mhin = fmaxf(mhi, thi);
        float sclo = __expf(mlo - mlon), schi = __expf(mhi - mhin);
        float psl = 0.f, psh = 0.f;
        unsigned pp[8][2];
#pragma unroll
        for (int nt = 0; nt < 8; nt++) {
            int col = j0 + nt * 8 + 2 * tg;
            float p0 = (full || col     < N_) ? __expf(s[nt][0] - mlon) : 0.f;
            float p1 = (full || col + 1 < N_) ? __expf(s[nt][1] - mlon) : 0.f;
            float p2 = (full || col     < N_) ? __expf(s[nt][2] - mhin) : 0.f;
            float p3 = (full || col + 1 < N_) ? __expf(s[nt][3] - mhin) : 0.f;
            psl += p0 + p1; psh += p2 + p3;
            o[nt][0] *= sclo; o[nt][1] *= sclo;
            o[nt][2] *= schi; o[nt][3] *= schi;
            pp[nt][0] = pack2(p0, p1);
            pp[nt][1] = pack2(p2, p3);
        }
#pragma unroll
        for (int off = 1; off <= 2; off <<= 1) {
            psl += __shfl_xor_sync(0xffffffffu, psl, off);
            psh += __shfl_xor_sync(0xffffffffu, psh, off);
        }
        zlo = zlo * sclo + psl;  zhi = zhi * schi + psh;
        mlo = mlon;  mhi = mhin;

        // ---- O += P @ V ;  Ob += bias @ V ----
#pragma unroll
        for (int kk = 0; kk < 4; kk++) {
            unsigned pa[4] = { pp[2 * kk][0], pp[2 * kk][1],
                               pp[2 * kk + 1][0], pp[2 * kk + 1][1] };
            unsigned ba[4];
            int jb = j0 + kk * 16 + 2 * tg;
            float b00 = (rlo < N_ && jb     < N_) ? RBs[576 + jb - rlo]     : 0.f;
            float b01 = (rlo < N_ && jb + 1 < N_) ? RBs[576 + jb + 1 - rlo] : 0.f;
            float b10 = (rhi < N_ && jb     < N_) ? RBs[576 + jb - rhi]     : 0.f;
            float b11 = (rhi < N_ && jb + 1 < N_) ? RBs[576 + jb + 1 - rhi] : 0.f;
            float b20 = (rlo < N_ && jb + 8 < N_) ? RBs[576 + jb + 8 - rlo] : 0.f;
            float b21 = (rlo < N_ && jb + 9 < N_) ? RBs[576 + jb + 9 - rlo] : 0.f;
            float b30 = (rhi < N_ && jb + 8 < N_) ? RBs[576 + jb + 8 - rhi] : 0.f;
            float b31 = (rhi < N_ && jb + 9 < N_) ? RBs[576 + jb + 9 - rhi] : 0.f;
            ba[0] = pack2(b00, b01); ba[1] = pack2(b10, b11);
            ba[2] = pack2(b20, b21); ba[3] = pack2(b30, b31);
#pragma unroll
            for (int nt = 0; nt < 8; nt++) {
                unsigned v0 = Vb[(nt * 8 + gr) * FKSTR + kk * 8 + tg];
                unsigned v1 = Vb[(nt * 8 + gr) * FKSTR + kk * 8 + tg + 4];
                mma16(o[nt],  pa, v0, v1);
                mma16(ob[nt], ba, v0, v1);
            }
        }
    }

    // ---- epilogue: (O/Z + Ob) -> fp16 g_ao16 ----
    float izlo = 1.f / zlo, izhi = 1.f / zhi;
#pragma unroll
    for (int nt = 0; nt < 8; nt++) {
        int col = h * 64 + nt * 8 + 2 * tg;
        if (rlo < N_)
            *(unsigned*)(g_ao16 + ((size_t)b * N_ + rlo) * 512 + col) =
                pack2(o[nt][0] * izlo + ob[nt][0], o[nt][1] * izlo + ob[nt][1]);
        if (rhi < N_)
            *(unsigned*)(g_ao16 + ((size_t)b * N_ + rhi) * 512 + col) =
                pack2(o[nt][2] * izhi + ob[nt][2], o[nt][3] * izhi + ob[nt][3]);
    }
#undef FL_ISSUE
}

// ================= launch =================
extern "C" void kernel_launch(void* const* d_in, const int* in_sizes, int n_in,
                              void* d_out, int out_size) {
    const float* x         = (const float*)d_in[0];
    const float* W_qk      = (const float*)d_in[1];
    const float* W_v       = (const float*)d_in[2];
    const float* W_out     = (const float*)d_in[3];
    const float* b_out     = (const float*)d_in[4];
    const float* rel_bias  = (const float*)d_in[5];
    const float* ema_delta = (const float*)d_in[6];
    const float* ema_alpha = (const float*)d_in[7];
    const float* ema_beta  = (const float*)d_in[8];
    const float* ema_gamma = (const float*)d_in[9];
    const float* ema_omega = (const float*)d_in[10];
    float* out = (float*)d_out;

    static int attr_set = 0;
    if (!attr_set) {
        cudaFuncSetAttribute(ema_fused, cudaFuncAttributeMaxDynamicSharedMemorySize,
                             ESM_TOTAL * (int)sizeof(float));
        cudaFuncSetAttribute(gemm_qkv_tc, cudaFuncAttributeMaxDynamicSharedMemorySize, GSMEM16_BYTES);
        cudaFuncSetAttribute(gemm_out_tc, cudaFuncAttributeMaxDynamicSharedMemorySize, GSMEM16_BYTES);
        cudaFuncSetAttribute(flash_attn_tc, cudaFuncAttributeMaxDynamicSharedMemorySize, FSMEM_BYTES);
        attr_set = 1;
    }

    coef_kernel<<<(2 * DIM_ * NDIM_ + 255) / 256, 256>>>(ema_delta, ema_alpha, ema_beta, ema_gamma);
    tcvt_kernel<<<(1024 * 512 + 255) / 256, 256>>>(W_qk, 0, 1024, 1024 * 512);
    tcvt_kernel<<<(512 * 512 + 255) / 256, 256>>>(W_v, 1, 512, 512 * 512);
    tcvt_kernel<<<(512 * 512 + 255) / 256, 256>>>(W_out, 2, 512, 512 * 512);
    ema_fused<<<dim3(DIM_ / 16, 1, B_), 256, ESM_TOTAL * sizeof(float)>>>(x, ema_omega);

    gemm_qkv_tc<<<GEMM_GRID, 128, GSMEM16_BYTES>>>();
    vt_kernel<<<dim3(VTP / 32, 16, B_), dim3(32, 8)>>>();

    flash_attn_tc<<<dim3((N_ + QROWS - 1) / QROWS, HEADS_, B_), 192, FSMEM_BYTES>>>(rel_bias);

    gemm_out_tc<<<GEMM_GRID, 128, GSMEM16_BYTES>>>(b_out, out);
}